// round 14
// baseline (speedup 1.0000x reference)
#include <cuda_runtime.h>
#include <math.h>
#include <stdint.h>
#include <cuda_fp16.h>

// Problem constants
#define BSZ 4
#define TT 1024
#define DD 768
#define HH 12
#define KH 64
#define LL 6
#define VV 32000
#define FF 3072
#define HD 9216
#define ROWS (BSZ*TT)  // 4096
#define L2E 1.44269504088896340736f

// ---------------- scratch ------------------------------------------------------
__device__ float  g_x[(size_t)ROWS*DD];
__device__ __half g_h[(size_t)ROWS*DD];
__device__ __half g_qk[(size_t)2*ROWS*DD];
__device__ __half g_v[(size_t)ROWS*HD];
__device__ __half g_o[(size_t)ROWS*HD];
__device__ __half g_p[(size_t)BSZ*HH*TT*TT];
__device__ __half g_f[(size_t)ROWS*FF];
__device__ float  g_sk[(size_t)2*ROWS*DD];
__device__ float  g_rl[ROWS];

// half weight cache
#define WQ_SZ  3538944
#define WV_SZ  42467328
#define WP_SZ  42467328
#define W1_SZ  14155776
#define WH_SZ  24576000
#define O_WQ   0
#define O_WK   (O_WQ + WQ_SZ)
#define O_WV   (O_WK + WQ_SZ)
#define O_WP   (O_WV + WV_SZ)
#define O_W1   (O_WP + WP_SZ)
#define O_W2   (O_W1 + W1_SZ)
#define O_WH   (O_W2 + W1_SZ)
#define WC_TOTAL (O_WH + WH_SZ)
__device__ __half g_wc[(size_t)WC_TOTAL];

// ---------------- helpers ------------------------------------------------------
__device__ __forceinline__ float fexp2(float x) {
    x = fmaxf(x, -126.f);
    float fi = floorf(x);
    float f = x - fi;
    float p = 1.f + f * (0.69314718f + f * (0.24022651f + f * (0.05550411f +
              f * (0.00961813f + f * 0.00133336f))));
    return __int_as_float(((int)fi + 127) << 23) * p;
}

__device__ __forceinline__ void mma_f16(float c[4], const uint32_t a[4], uint32_t b0, uint32_t b1) {
    asm volatile(
        "mma.sync.aligned.m16n8k16.row.col.f32.f16.f16.f32 "
        "{%0,%1,%2,%3},{%4,%5,%6,%7},{%8,%9},{%0,%1,%2,%3};"
        : "+f"(c[0]), "+f"(c[1]), "+f"(c[2]), "+f"(c[3])
        : "r"(a[0]), "r"(a[1]), "r"(a[2]), "r"(a[3]), "r"(b0), "r"(b1));
}
__device__ __forceinline__ void ldsm4(uint32_t r[4], uint32_t addr) {
    asm volatile("ldmatrix.sync.aligned.m8n8.x4.shared.b16 {%0,%1,%2,%3}, [%4];"
        : "=r"(r[0]), "=r"(r[1]), "=r"(r[2]), "=r"(r[3]) : "r"(addr));
}
__device__ __forceinline__ void ldsm4t(uint32_t r[4], uint32_t addr) {
    asm volatile("ldmatrix.sync.aligned.m8n8.x4.trans.shared.b16 {%0,%1,%2,%3}, [%4];"
        : "=r"(r[0]), "=r"(r[1]), "=r"(r[2]), "=r"(r[3]) : "r"(addr));
}
#define CP16(dst, src) asm volatile("cp.async.cg.shared.global [%0], [%1], 16;" :: "r"(dst), "l"(src))
#define CP_COMMIT() asm volatile("cp.async.commit_group;")
#define CP_WAIT2() asm volatile("cp.async.wait_group 2;")
#define CP_WAIT0() asm volatile("cp.async.wait_group 0;")

// ---------------- small kernels ------------------------------------------------
__global__ void cvt_k(const float4* __restrict__ s, uint2* __restrict__ d, size_t n4) {
    size_t i = (size_t)blockIdx.x * blockDim.x + threadIdx.x;
    size_t stride = (size_t)gridDim.x * blockDim.x;
    for (; i < n4; i += stride) {
        float4 v = s[i];
        __half2 h0 = __floats2half2_rn(v.x, v.y);
        __half2 h1 = __floats2half2_rn(v.z, v.w);
        uint2 o;
        o.x = *(uint32_t*)&h0;
        o.y = *(uint32_t*)&h1;
        d[i] = o;
    }
}

__global__ void embed_k(const int* __restrict__ ids, const float* __restrict__ tok,
                        const float* __restrict__ pos, float* __restrict__ x) {
    int row = blockIdx.x;
    int t = row % TT;
    int id = ids[row];
    const float* te = tok + (size_t)id * DD;
    const float* pe = pos + (size_t)t * DD;
    float* xr = x + (size_t)row * DD;
    for (int i = threadIdx.x; i < DD; i += blockDim.x)
        xr[i] = te[i] + pe[i];
}

__global__ __launch_bounds__(256)
void ln_k(const float* __restrict__ x, __half* __restrict__ y,
          const float* __restrict__ g, const float* __restrict__ b) {
    int wid = threadIdx.x >> 5, lane = threadIdx.x & 31;
    int row = blockIdx.x * 8 + wid;
    const float* xr = x + (size_t)row * DD;
    float4 vv[6];
    float sum = 0.f, sq = 0.f;
#pragma unroll
    for (int i = 0; i < 6; i++) {
        vv[i] = *(const float4*)(xr + i * 128 + lane * 4);
        sum += vv[i].x + vv[i].y + vv[i].z + vv[i].w;
        sq  += vv[i].x*vv[i].x + vv[i].y*vv[i].y + vv[i].z*vv[i].z + vv[i].w*vv[i].w;
    }
#pragma unroll
    for (int o = 16; o; o >>= 1) {
        sum += __shfl_xor_sync(~0u, sum, o);
        sq  += __shfl_xor_sync(~0u, sq, o);
    }
    float mu = sum * (1.0f / DD);
    float var = sq * (1.0f / DD) - mu * mu;
    float rstd = rsqrtf(var + 1e-5f);
    __half* yr = y + (size_t)row * DD;
#pragma unroll
    for (int i = 0; i < 6; i++) {
        int c = i * 128 + lane * 4;
        float4 gg = *(const float4*)(g + c);
        float4 bb = *(const float4*)(b + c);
        __half2 h0 = __floats2half2_rn((vv[i].x - mu) * rstd * gg.x + bb.x,
                                       (vv[i].y - mu) * rstd * gg.y + bb.y);
        __half2 h1 = __floats2half2_rn((vv[i].z - mu) * rstd * gg.z + bb.z,
                                       (vv[i].w - mu) * rstd * gg.w + bb.w);
        uint2 o;
        o.x = *(uint32_t*)&h0; o.y = *(uint32_t*)&h1;
        *(uint2*)(yr + c) = o;
    }
}

// fused split-K combine + layernorm: x += s0+s1+bias; y = LN(x)
__global__ __launch_bounds__(256)
void addskln_k(const float4* __restrict__ s0, const float4* __restrict__ s1,
               const float* __restrict__ bias, float4* __restrict__ x,
               const float* __restrict__ g, const float* __restrict__ b,
               __half* __restrict__ y) {
    int wid = threadIdx.x >> 5, lane = threadIdx.x & 31;
    int row = blockIdx.x * 8 + wid;
    size_t b4 = (size_t)row * (DD / 4);
    float4 vv[6];
    float sum = 0.f, sq = 0.f;
#pragma unroll
    for (int i = 0; i < 6; i++) {
        int c4 = i * 32 + lane;
        float4 a = s0[b4 + c4], bb = s1[b4 + c4], c = x[b4 + c4];
        float4 bi = *(const float4*)(bias + c4 * 4);
        c.x += a.x + bb.x + bi.x;
        c.y += a.y + bb.y + bi.y;
        c.z += a.z + bb.z + bi.z;
        c.w += a.w + bb.w + bi.w;
        x[b4 + c4] = c;
        vv[i] = c;
        sum += c.x + c.y + c.z + c.w;
        sq  += c.x*c.x + c.y*c.y + c.z*c.z + c.w*c.w;
    }
#pragma unroll
    for (int o = 16; o; o >>= 1) {
        sum += __shfl_xor_sync(~0u, sum, o);
        sq  += __shfl_xor_sync(~0u, sq, o);
    }
    float mu = sum * (1.0f / DD);
    float var = sq * (1.0f / DD) - mu * mu;
    float rstd = rsqrtf(var + 1e-5f);
    __half* yr = y + (size_t)row * DD;
#pragma unroll
    for (int i = 0; i < 6; i++) {
        int c = i * 128 + lane * 4;
        float4 gg = *(const float4*)(g + c);
        float4 bb = *(const float4*)(b + c);
        __half2 h0 = __floats2half2_rn((vv[i].x - mu) * rstd * gg.x + bb.x,
                                       (vv[i].y - mu) * rstd * gg.y + bb.y);
        __half2 h1 = __floats2half2_rn((vv[i].z - mu) * rstd * gg.z + bb.z,
                                       (vv[i].w - mu) * rstd * gg.w + bb.w);
        uint2 o;
        o.x = *(uint32_t*)&h0; o.y = *(uint32_t*)&h1;
        *(uint2*)(yr + c) = o;
    }
}

// ---------------- fp16 GEMM 128x128 (cp.async 4-stage, BK=32) ------------------
// flags: 1 bias, 2 relu, 4 accumulate(fp32 C), 8 causal-K, 32 store-half
#define AP 40
#define ABYTES (128*AP*2)
#define BP 136
#define BBYTES (32*BP*2)
#define STGB (ABYTES+BBYTES)      // 18944
#define NSTG 4
#define GSMEM (NSTG*STGB)         // 75776
__global__ __launch_bounds__(256, 2)
void gemm_hc(const __half* __restrict__ A, const __half* __restrict__ Bm,
             void* __restrict__ Cv,
             int K, int lda, int ldb, int ldc,
             int Nh, size_t hstride,
             const float* __restrict__ bias, int flags,
             int batchH,
             size_t aOuter, size_t aInner,
             size_t bOuter, size_t bInner,
             size_t cOuter, size_t cInner) {
    extern __shared__ __align__(16) char smem[];
    int z = blockIdx.z;
    int zo = z / batchH, zi = z - zo * batchH;
    A  += zo * aOuter + zi * aInner;
    Bm += zo * bOuter + zi * bInner;
    const size_t cOff = (size_t)zo * cOuter + (size_t)zi * cInner;

    const int tid  = threadIdx.x;
    const int lane = tid & 31;
    const int warp = tid >> 5;
    const int wm = warp >> 2;
    const int wn = warp & 3;
    const int m0 = blockIdx.y * 128;
    const int n0 = blockIdx.x * 128;

    int Kc = K;
    if (flags & 8) { int ke = (blockIdx.y + 1) * 128; if (ke < Kc) Kc = ke; }
    const int steps = Kc >> 5;

    const int ar0 = tid >> 2,  ac8 = (tid & 3);
    const int br0 = tid >> 4,  bc8 = (tid & 15);
    const __half* aP0 = A + (size_t)(m0 + ar0) * lda + ac8 * 8;
    const __half* aP1 = A + (size_t)(m0 + ar0 + 64) * lda + ac8 * 8;
    const int gcol = n0 + bc8 * 8;
    const __half* bPB = Bm + (size_t)(gcol / Nh) * hstride + (size_t)(gcol % Nh);

    const uint32_t base = (uint32_t)__cvta_generic_to_shared(smem);
    const uint32_t aD0 = base + (uint32_t)(ar0 * 80 + ac8 * 16);
    const uint32_t aD1 = aD0 + 64 * 80;
    const uint32_t bD0 = base + (uint32_t)(ABYTES + br0 * 272 + bc8 * 16);
    const uint32_t bD1 = bD0 + 16 * 272;

    float acc[4][4][4];
#pragma unroll
    for (int mt = 0; mt < 4; mt++)
#pragma unroll
        for (int nt = 0; nt < 4; nt++)
#pragma unroll
            for (int i = 0; i < 4; i++) acc[mt][nt][i] = 0.f;

    const uint32_t aF = base + (uint32_t)(((wm * 64 + (lane & 15)) * AP + (lane >> 4) * 8) * 2);
    const uint32_t bF = base + (uint32_t)(ABYTES +
        (((lane & 7) + ((lane >> 3) & 1) * 8) * BP + wn * 32 + (lane >> 4) * 8) * 2);

#pragma unroll
    for (int pt = 0; pt < NSTG - 1; pt++) {
        if (pt < steps) {
            const uint32_t so = (uint32_t)(pt * STGB);
            const int k0 = pt << 5;
            CP16(aD0 + so, aP0 + k0);
            CP16(aD1 + so, aP1 + k0);
            CP16(bD0 + so, bPB + (size_t)(k0 + br0) * ldb);
            CP16(bD1 + so, bPB + (size_t)(k0 + br0 + 16) * ldb);
        }
        CP_COMMIT();
    }

    int stg = 0;
    for (int s = 0; s < steps; s++) {
        CP_WAIT2();
        __syncthreads();
        {
            const int nt_ = s + NSTG - 1;
            if (nt_ < steps) {
                int ns = stg + NSTG - 1; if (ns >= NSTG) ns -= NSTG;
                const uint32_t so = (uint32_t)(ns * STGB);
                const int k0 = nt_ << 5;
                CP16(aD0 + so, aP0 + k0);
                CP16(aD1 + so, aP1 + k0);
                CP16(bD0 + so, bPB + (size_t)(k0 + br0) * ldb);
                CP16(bD1 + so, bPB + (size_t)(k0 + br0 + 16) * ldb);
            }
            CP_COMMIT();
        }

        const uint32_t aS = aF + (uint32_t)(stg * STGB);
        const uint32_t bS = bF + (uint32_t)(stg * STGB);
#pragma unroll
        for (int ks = 0; ks < 2; ks++) {
            uint32_t af[4][4];
#pragma unroll
            for (int mt = 0; mt < 4; mt++)
                ldsm4(af[mt], aS + (uint32_t)(mt * 16 * AP * 2 + ks * 32));
            uint32_t bf[2][4];
            ldsm4t(bf[0], bS + (uint32_t)(ks * 16 * BP * 2));
            ldsm4t(bf[1], bS + (uint32_t)(ks * 16 * BP * 2 + 32));
#pragma unroll
            for (int nt = 0; nt < 4; nt++) {
                uint32_t b0 = bf[nt >> 1][(nt & 1) * 2];
                uint32_t b1 = bf[nt >> 1][(nt & 1) * 2 + 1];
#pragma unroll
                for (int mt = 0; mt < 4; mt++)
                    mma_f16(acc[mt][nt], af[mt], b0, b1);
            }
        }
        stg++; if (stg >= NSTG) stg = 0;
    }

#pragma unroll
    for (int mt = 0; mt < 4; mt++) {
        const int row = m0 + wm * 64 + mt * 16 + (lane >> 2);
#pragma unroll
        for (int nt = 0; nt < 4; nt++) {
            const int col = n0 + wn * 32 + nt * 8 + (lane & 3) * 2;
            float2 bi = make_float2(0.f, 0.f);
            if (flags & 1) bi = *(const float2*)(bias + col);
            float2 v0 = make_float2(acc[mt][nt][0] + bi.x, acc[mt][nt][1] + bi.y);
            float2 v1 = make_float2(acc[mt][nt][2] + bi.x, acc[mt][nt][3] + bi.y);
            if (flags & 2) {
                v0.x = fmaxf(v0.x, 0.f); v0.y = fmaxf(v0.y, 0.f);
                v1.x = fmaxf(v1.x, 0.f); v1.y = fmaxf(v1.y, 0.f);
            }
            if (flags & 32) {
                __half* Ch = (__half*)Cv + cOff;
                *(__half2*)(Ch + (size_t)row * ldc + col) = __floats2half2_rn(v0.x, v0.y);
                *(__half2*)(Ch + (size_t)(row + 8) * ldc + col) = __floats2half2_rn(v1.x, v1.y);
            } else {
                float* Cf = (float*)Cv + cOff;
                float* c0 = Cf + (size_t)row * ldc + col;
                float* c1 = Cf + (size_t)(row + 8) * ldc + col;
                if (flags & 4) {
                    float2 o0 = *(float2*)c0, o1 = *(float2*)c1;
                    v0.x += o0.x; v0.y += o0.y; v1.x += o1.x; v1.y += o1.y;
                }
                *(float2*)c0 = v0;
                *(float2*)c1 = v1;
            }
        }
    }
}

// ---------------- fp16 GEMM 256x128 big-tile (1 CTA/SM, warp 64x64) ------------
// flags: 1 bias, 2 relu, 32 store-half (no causal/acc paths)
#define BG_ABYTES (256*AP*2)          // 20480
#define BG_STGB (BG_ABYTES+BBYTES)    // 29184
#define BG_SMEM (NSTG*BG_STGB)        // 116736
__global__ __launch_bounds__(256, 1)
void gemm_big(const __half* __restrict__ A, const __half* __restrict__ Bm,
              void* __restrict__ Cv,
              int K, int lda, int ldb, int ldc,
              int Nh, size_t hstride,
              const float* __restrict__ bias, int flags) {
    extern __shared__ __align__(16) char smem[];
    const int tid  = threadIdx.x;
    const int lane = tid & 31;
    const int warp = tid >> 5;
    const int wmi = warp & 3;       // 4 warps along M (64 rows each)
    const int wni = warp >> 2;      // 2 warps along N (64 cols each)
    const int m0 = blockIdx.y * 256;
    const int n0 = blockIdx.x * 128;
    const int steps = K >> 5;

    const int ar0 = tid >> 2,  ac8 = (tid & 3);    // A rows 0..63 (+64i), 4 chunks/row
    const int br0 = tid >> 4,  bc8 = (tid & 15);   // B rows 0..15 (+16i)
    const __half* aPb = A + (size_t)(m0 + ar0) * lda + ac8 * 8;
    const int gcol = n0 + bc8 * 8;
    const __half* bPB = Bm + (size_t)(gcol / Nh) * hstride + (size_t)(gcol % Nh);

    const uint32_t base = (uint32_t)__cvta_generic_to_shared(smem);
    const uint32_t aD = base + (uint32_t)(ar0 * 80 + ac8 * 16);
    const uint32_t bD0 = base + (uint32_t)(BG_ABYTES + br0 * 272 + bc8 * 16);
    const uint32_t bD1 = bD0 + 16 * 272;

    float acc[4][8][4];
#pragma unroll
    for (int mt = 0; mt < 4; mt++)
#pragma unroll
        for (int nt = 0; nt < 8; nt++)
#pragma unroll
            for (int i = 0; i < 4; i++) acc[mt][nt][i] = 0.f;

    const uint32_t aF = base + (uint32_t)(((wmi * 64 + (lane & 15)) * AP + (lane >> 4) * 8) * 2);
    const uint32_t bF = base + (uint32_t)(BG_ABYTES +
        (((lane & 7) + ((lane >> 3) & 1) * 8) * BP + wni * 64 + (lane >> 4) * 8) * 2);

#pragma unroll
    for (int pt = 0; pt < NSTG - 1; pt++) {
        if (pt < steps) {
            const uint32_t so = (uint32_t)(pt * BG_STGB);
            const int k0 = pt << 5;
#pragma unroll
            for (int i = 0; i < 4; i++)
                CP16(aD + so + (uint32_t)(i * 64 * 80), aPb + (size_t)(i * 64) * lda + k0);
            CP16(bD0 + so, bPB + (size_t)(k0 + br0) * ldb);
            CP16(bD1 + so, bPB + (size_t)(k0 + br0 + 16) * ldb);
        }
        CP_COMMIT();
    }

    int stg = 0;
    for (int s = 0; s < steps; s++) {
        CP_WAIT2();
        __syncthreads();
        {
            const int nt_ = s + NSTG - 1;
            if (nt_ < steps) {
                int ns = stg + NSTG - 1; if (ns >= NSTG) ns -= NSTG;
                const uint32_t so = (uint32_t)(ns * BG_STGB);
                const int k0 = nt_ << 5;
#pragma unroll
                for (int i = 0; i < 4; i++)
                    CP16(aD + so + (uint32_t)(i * 64 * 80), aPb + (size_t)(i * 64) * lda + k0);
                CP16(bD0 + so, bPB + (size_t)(k0 + br0) * ldb);
                CP16(bD1 + so, bPB + (size_t)(k0 + br0 + 16) * ldb);
            }
            CP_COMMIT();
        }

        const uint32_t aS = aF + (uint32_t)(stg * BG_STGB);
        const uint32_t bS = bF + (uint32_t)(stg * BG_STGB);
#pragma unroll
        for (int ks = 0; ks < 2; ks++) {
            uint32_t af[4][4];
#pragma unroll
            for (int mt = 0; mt < 4; mt++)
                ldsm4(af[mt], aS + (uint32_t)(mt * 16 * AP * 2 + ks * 32));
            uint32_t bf[4][4];
#pragma unroll
            for (int j = 0; j < 4; j++)
                ldsm4t(bf[j], bS + (uint32_t)(ks * 16 * BP * 2 + j * 32));
#pragma unroll
            for (int nt = 0; nt < 8; nt++) {
                uint32_t b0 = bf[nt >> 1][(nt & 1) * 2];
                uint32_t b1 = bf[nt >> 1][(nt & 1) * 2 + 1];
#pragma unroll
                for (int mt = 0; mt < 4; mt++)
                    mma_f16(acc[mt][nt], af[mt], b0, b1);
            }
        }
        stg++; if (stg >= NSTG) stg = 0;
    }

#pragma unroll
    for (int mt = 0; mt < 4; mt++) {
        const int row = m0 + wmi * 64 + mt * 16 + (lane >> 2);
#pragma unroll
        for (int nt = 0; nt < 8; nt++) {
            const int col = n0 + wni * 64 + nt * 8 + (lane & 3) * 2;
            float2 bi = make_float2(0.f, 0.f);
            if (flags & 1) bi = *(const float2*)(bias + col);
            float2 v0 = make_float2(acc[mt][nt][0] + bi.x, acc[mt][nt][1] + bi.y);
            float2 v1 = make_float2(acc[mt][nt][2] + bi.x, acc[mt][nt][3] + bi.y);
            if (flags & 2) {
                v0.x = fmaxf(v0.x, 0.f); v0.y = fmaxf(v0.y, 0.f);
                v1.x = fmaxf(v1.x, 0.f); v1.y = fmaxf(v1.y, 0.f);
            }
            if (flags & 32) {
                __half* Ch = (__half*)Cv;
                *(__half2*)(Ch + (size_t)row * ldc + col) = __floats2half2_rn(v0.x, v0.y);
                *(__half2*)(Ch + (size_t)(row + 8) * ldc + col) = __floats2half2_rn(v1.x, v1.y);
            } else {
                float* Cf = (float*)Cv;
                *(float2*)(Cf + (size_t)row * ldc + col) = v0;
                *(float2*)(Cf + (size_t)(row + 8) * ldc + col) = v1;
            }
        }
    }
}

// ---------------- attention scores (fp16 tensor cores) --------------------------
#define QP 72
#define QBYTES (128*QP*2)
#define SSMEM (2*QBYTES)
__global__ __launch_bounds__(256, 2)
void score_tc(const __half* __restrict__ q, const __half* __restrict__ k,
              __half* __restrict__ p) {
    extern __shared__ __align__(16) char ss[];
    const int z = blockIdx.z;
    const int b = z / HH, h = z - b * HH;
    const int m0 = blockIdx.y * 128;
    const int n0 = blockIdx.x * 128;
    if (n0 > m0 + 127) return;

    const int tid  = threadIdx.x;
    const int lane = tid & 31;
    const int warp = tid >> 5;
    const int wm = warp >> 2;
    const int wn = warp & 3;

    const __half* qb = q + ((size_t)(b * TT + m0)) * DD + h * KH;
    const __half* kb = k + ((size_t)(b * TT + n0)) * DD + h * KH;

    const uint32_t base = (uint32_t)__cvta_generic_to_shared(ss);
#pragma unroll
    for (int i = 0; i < 4; i++) {
        int c = tid + i * 256;
        int row = c >> 3;
        int cg = c & 7;
        CP16(base + (uint32_t)(row * 144 + cg * 16), qb + (size_t)row * DD + cg * 8);
        CP16(base + (uint32_t)(QBYTES + row * 144 + cg * 16), kb + (size_t)row * DD + cg * 8);
    }
    CP_COMMIT();
    CP_WAIT0();
    __syncthreads();

    float acc[4][4][4];
#pragma unroll
    for (int mt = 0; mt < 4; mt++)
#pragma unroll
        for (int nt = 0; nt < 4; nt++)
#pragma unroll
            for (int i = 0; i < 4; i++) acc[mt][nt][i] = 0.f;

    const uint32_t qF = base + (uint32_t)(((wm * 64 + (lane & 15)) * QP + (lane >> 4) * 8) * 2);
    const uint32_t kF = base + (uint32_t)(QBYTES +
        ((wn * 32 + (lane & 7) + (lane >> 4) * 8) * QP + ((lane >> 3) & 1) * 8) * 2);

#pragma unroll
    for (int ks = 0; ks < 4; ks++) {
        uint32_t af[4][4];
#pragma unroll
        for (int mt = 0; mt < 4; mt++)
            ldsm4(af[mt], qF + (uint32_t)(mt * 16 * QP * 2 + ks * 32));
        uint32_t bf[2][4];
        ldsm4(bf[0], kF + (uint32_t)(ks * 32));
        ldsm4(bf[1], kF + (uint32_t)(16 * QP * 2 + ks * 32));
#pragma unroll
        for (int nt = 0; nt < 4; nt++) {
            uint32_t b0 = bf[nt >> 1][(nt & 1) * 2];
            uint32_t b1 = bf[nt >> 1][(nt & 1) * 2 + 1];
#pragma unroll
            for (int mt = 0; mt < 4; mt++)
                mma_f16(acc[mt][nt], af[mt], b0, b1);
        }
    }

    __half* pz = p + (size_t)z * TT * TT;
#pragma unroll
    for (int mt = 0; mt < 4; mt++) {
        const int row = m0 + wm * 64 + mt * 16 + (lane >> 2);
#pragma unroll
        for (int nt = 0; nt < 4; nt++) {
            const int col = n0 + wn * 32 + nt * 8 + (lane & 3) * 2;
            __half2 h0 = __floats2half2_rn(acc[mt][nt][0] * 0.125f, acc[mt][nt][1] * 0.125f);
            __half2 h1 = __floats2half2_rn(acc[mt][nt][2] * 0.125f, acc[mt][nt][3] * 0.125f);
            *(__half2*)(pz + (size_t)row * TT + col) = h0;
            *(__half2*)(pz + (size_t)(row + 8) * TT + col) = h1;
        }
    }
}

// ---------------- causal softmax: one warp per row ------------------------------
__global__ __launch_bounds__(256)
void attn_sm(__half* __restrict__ p) {
    const int wid = threadIdx.x >> 5, lane = threadIdx.x & 31;
    const int t = blockIdx.x * 8 + wid;
    const int h = blockIdx.y, b = blockIdx.z;
    __half* row = p + ((size_t)((b * HH + h) * TT + t)) * TT;
    const int valid = t + 1;
    const int nj = (t >> 7) + 1;

    float4 v[8];
    float m = -INFINITY;
#pragma unroll
    for (int j = 0; j < 8; j++) {
        if (j < nj) {
            int c0 = j * 128 + lane * 4;
            uint2 u = *(const uint2*)(row + c0);
            float2 f0 = __half22float2(*(__half2*)&u.x);
            float2 f1 = __half22float2(*(__half2*)&u.y);
            float4 val;
            val.x = (c0 + 0 < valid) ? f0.x : -INFINITY;
            val.y = (c0 + 1 < valid) ? f0.y : -INFINITY;
            val.z = (c0 + 2 < valid) ? f1.x : -INFINITY;
            val.w = (c0 + 3 < valid) ? f1.y : -INFINITY;
            v[j] = val;
            m = fmaxf(m, fmaxf(fmaxf(val.x, val.y), fmaxf(val.z, val.w)));
        }
    }
#pragma unroll
    for (int o = 16; o; o >>= 1) m = fmaxf(m, __shfl_xor_sync(~0u, m, o));

    float sum = 0.f;
#pragma unroll
    for (int j = 0; j < 8; j++) {
        if (j < nj) {
            float4 e;
            e.x = fexp2((v[j].x - m) * L2E);
            e.y = fexp2((v[j].y - m) * L2E);
            e.z = fexp2((v[j].z - m) * L2E);
            e.w = fexp2((v[j].w - m) * L2E);
            v[j] = e;
            sum += e.x + e.y + e.z + e.w;
        }
    }
#pragma unroll
    for (int o = 16; o; o >>= 1) sum += __shfl_xor_sync(~0u, sum, o);
    float inv = 1.f / sum;
#pragma unroll
    for (int j = 0; j < 8; j++) {
        if (j < nj) {
            int c0 = j * 128 + lane * 4;
            __half2 h0 = __floats2half2_rn(v[j].x * inv, v[j].y * inv);
            __half2 h1 = __floats2half2_rn(v[j].z * inv, v[j].w * inv);
            uint2 u;
            u.x = *(uint32_t*)&h0; u.y = *(uint32_t*)&h1;
            *(uint2*)(row + c0) = u;
        }
    }
}

// ---------------- loss ----------------------------------------------------------
__global__ void loss_row_k(const float* __restrict__ logits, const int* __restrict__ tgt,
                           float* __restrict__ rl) {
    int row = blockIdx.x, tid = threadIdx.x;
    const float4* lr4 = (const float4*)(logits + (size_t)row * VV);
    __shared__ float red[256];
    float m = -INFINITY;
    for (int i = tid; i < VV / 4; i += 256) {
        float4 v = lr4[i];
        m = fmaxf(m, fmaxf(fmaxf(v.x, v.y), fmaxf(v.z, v.w)));
    }
    red[tid] = m; __syncthreads();
    for (int s = 128; s > 0; s >>= 1) { if (tid < s) red[tid] = fmaxf(red[tid], red[tid + s]); __syncthreads(); }
    m = red[0]; __syncthreads();
    float sum = 0.f;
    for (int i = tid; i < VV / 4; i += 256) {
        float4 v = lr4[i];
        sum += fexp2((v.x - m) * L2E) + fexp2((v.y - m) * L2E)
             + fexp2((v.z - m) * L2E) + fexp2((v.w - m) * L2E);
    }
    red[tid] = sum; __syncthreads();
    for (int s = 128; s > 0; s >>= 1) { if (tid < s) red[tid] += red[tid + s]; __syncthreads(); }
    if (tid == 0) {
        float lse = m + logf(red[0]);
        rl[row] = lse - logits[(size_t)row * VV + tgt[row]];
    }
}

__global__ void loss_final_k(const float* __restrict__ rl, float* __restrict__ out) {
    __shared__ float red[256];
    int tid = threadIdx.x;
    float s = 0.f;
    for (int i = tid; i < ROWS; i += 256) s += rl[i];
    red[tid] = s; __syncthreads();
    for (int k = 128; k > 0; k >>= 1) { if (tid < k) red[tid] += red[tid + k]; __syncthreads(); }
    if (tid == 0) out[0] = red[0] * (1.0f / ROWS);
}

__global__ void fill0_k(float* p, size_t n) {
    size_t i = (size_t)blockIdx.x * blockDim.x + threadIdx.x;
    if (i < n) p[i] = 0.f;
}

// ---------------- host-side launchers ------------------------------------------
static inline void gemm(const __half* A, const __half* B, void* C,
                        int M, int N, int K, int lda, int ldb, int ldc,
                        int Nh, size_t hs, const float* bias, int flags,
                        int batch = 1, int batchH = 1,
                        size_t aO = 0, size_t aI = 0,
                        size_t bO = 0, size_t bI = 0,
                        size_t cO = 0, size_t cI = 0) {
    dim3 grid(N / 128, M / 128, batch);
    gemm_hc<<<grid, 256, GSMEM>>>(A, B, C, K, lda, ldb, ldc, Nh, hs, bias, flags,
                                  batchH, aO, aI, bO, bI, cO, cI);
}
static inline void gemmB(const __half* A, const __half* B, void* C,
                         int M, int N, int K, int lda, int ldb, int ldc,
                         int Nh, size_t hs, const float* bias, int flags) {
    dim3 grid(N / 128, M / 256);
    gemm_big<<<grid, 256, BG_SMEM>>>(A, B, C, K, lda, ldb, ldc, Nh, hs, bias, flags);
}

extern "C" void kernel_launch(void* const* d_in, const int* in_sizes, int n_in,
                              void* d_out, int out_size) {
    const int*   ids   = (const int*)d_in[0];
    const int*   tgt   = (const int*)d_in[1];
    const float* tok   = (const float*)d_in[2];
    const float* pos   = (const float*)d_in[3];
    const float* Wq_i  = (const float*)d_in[4];
    const float* Wk_i  = (const float*)d_in[5];
    const float* Wv_i  = (const float*)d_in[6];
    const float* Wp_i  = (const float*)d_in[7];
    const float* bproj = (const float*)d_in[8];
    const float* ln1g  = (const float*)d_in[9];
    const float* ln1b  = (const float*)d_in[10];
    const float* ln2g  = (const float*)d_in[11];
    const float* ln2b  = (const float*)d_in[12];
    const float* W1_i  = (const float*)d_in[13];
    const float* b1    = (const float*)d_in[14];
    const float* W2_i  = (const float*)d_in[15];
    const float* b2    = (const float*)d_in[16];
    const float* lnfg  = (const float*)d_in[17];
    const float* lnfb  = (const float*)d_in[18];
    const float* Wh_i  = (const float*)d_in[19];
    const float* bhead = (const float*)d_in[20];

    float *x, *sk, *rl;
    __half *h, *qk, *v, *o, *p, *f, *wc;
    cudaGetSymbolAddress((void**)&x, g_x);
    cudaGetSymbolAddress((void**)&h, g_h);
    cudaGetSymbolAddress((void**)&qk, g_qk);
    cudaGetSymbolAddress((void**)&v, g_v);
    cudaGetSymbolAddress((void**)&o, g_o);
    cudaGetSymbolAddress((void**)&p, g_p);
    cudaGetSymbolAddress((void**)&f, g_f);
    cudaGetSymbolAddress((void**)&sk, g_sk);
    cudaGetSymbolAddress((void**)&rl, g_rl);
    cudaGetSymbolAddress((void**)&wc, g_wc);

    static bool attrSet = false;
    if (!attrSet) {
        cudaFuncSetAttribute(gemm_hc, cudaFuncAttributeMaxDynamicSharedMemorySize, GSMEM);
        cudaFuncSetAttribute(gemm_big, cudaFuncAttributeMaxDynamicSharedMemorySize, BG_SMEM);
        cudaFuncSetAttribute(score_tc, cudaFuncAttributeMaxDynamicSharedMemorySize, SSMEM);
        attrSet = true;
    }

    __half* Wq = wc + O_WQ;  __half* Wk = wc + O_WK;  __half* Wv = wc + O_WV;
    __half* Wp = wc + O_WP;  __half* W1 = wc + O_W1;  __half* W2 = wc + O_W2;
    __half* Wh = wc + O_WH;
    __half* q = qk;
    __half* k = qk + (size_t)ROWS * DD;

    float* out = (float*)d_out;
    const size_t NL = (size_t)ROWS * VV;

    embed_k<<<ROWS, 256>>>(ids, tok, pos, x);
    cvt_k<<<1024, 256>>>((const float4*)Wq_i, (uint2*)Wq, (size_t)WQ_SZ / 4);
    cvt_k<<<1024, 256>>>((const float4*)Wk_i, (uint2*)Wk, (size_t)WQ_SZ / 4);
    ln_k<<<ROWS / 8, 256>>>(x, h, ln1g, ln1b);
    cvt_k<<<2048, 256>>>((const float4*)Wv_i, (uint2*)Wv, (size_t)WV_SZ / 4);
    // merged q/k projection for layer 0
    gemm(h, Wq, q, ROWS, DD, DD, DD, KH, DD, KH, (size_t)DD * KH, nullptr, 32,
         2, 1, 0, 0, (size_t)WQ_SZ, 0, (size_t)ROWS * DD, 0);
    cvt_k<<<2048, 256>>>((const float4*)Wp_i, (uint2*)Wp, (size_t)WP_SZ / 4);
    cvt_k<<<1024, 256>>>((const float4*)W1_i, (uint2*)W1, (size_t)W1_SZ / 4);
    cvt_k<<<1024, 256>>>((const float4*)W2_i, (uint2*)W2, (size_t)W1_SZ / 4);
    cvt_k<<<2048, 256>>>((const float4*)Wh_i, (uint2*)Wh, (size_t)WH_SZ / 4);

    for (int l = 0; l < LL; l++) {
        if (l > 0) {
            gemm(h, Wq + (size_t)l * HH * DD * KH, q, ROWS, DD, DD, DD, KH, DD,
                 KH, (size_t)DD * KH, nullptr, 32,
                 2, 1, 0, 0, (size_t)WQ_SZ, 0, (size_t)ROWS * DD, 0);
        }
        // v projection on big-tile kernel
        gemmB(h, Wv + (size_t)l * HH * DD * DD, v, ROWS, HD, DD, DD, DD, HD,
              DD, (size_t)DD * DD, nullptr, 32);
        {
            dim3 grid(TT / 128, TT / 128, BSZ * HH);
            score_tc<<<grid, 256, SSMEM>>>(q, k, p);
            dim3 grid2(TT / 8, HH, BSZ);
            attn_sm<<<grid2, 256>>>(p);
        }
        gemm(p, v, o, TT, DD, TT, TT, HD, HD, DD, 0, nullptr, 8 | 32,
             BSZ * HH, HH,
             (size_t)HH * TT * TT, (size_t)TT * TT,
             (size_t)TT * HD, (size_t)DD,
             (size_t)TT * HD, (size_t)DD);
        // proj: split-K x2 (fp32 partials), fused combine + ln2 -> h
        gemm(o, Wp + (size_t)l * HD * DD, sk, ROWS, DD, HD / 2, HD, DD, DD,
             DD, 0, nullptr, 0,
             2, 1, (size_t)(HD / 2), 0, (size_t)(HD / 2) * DD, 0, (size_t)ROWS * DD, 0);
        addskln_k<<<ROWS / 8, 256>>>((const float4*)sk,
                                     (const float4*)(sk + (size_t)ROWS * DD),
                                     bproj + l * DD, (float4*)x,
                                     ln2g + l * DD, ln2b + l * DD, h);
        // W1 on big-tile kernel
        gemmB(h, W1 + (size_t)l * DD * FF, f, ROWS, FF, DD, DD, FF, FF,
              FF, 0, b1 + l * FF, 1 | 2 | 32);
        gemm(f, W2 + (size_t)l * FF * DD, sk, ROWS, DD, FF / 2, FF, DD, DD,
             DD, 0, nullptr, 0,
             2, 1, (size_t)(FF / 2), 0, (size_t)(FF / 2) * DD, 0, (size_t)ROWS * DD, 0);
        const float* ng = (l + 1 < LL) ? (ln1g + (l + 1) * DD) : lnfg;
        const float* nb = (l + 1 < LL) ? (ln1b + (l + 1) * DD) : lnfb;
        addskln_k<<<ROWS / 8, 256>>>((const float4*)sk,
                                     (const float4*)(sk + (size_t)ROWS * DD),
                                     b2 + l * DD, (float4*)x, ng, nb, h);
    }

    // head on big-tile kernel (fp32 out + bias)
    gemmB(h, Wh, out, ROWS, VV, DD, DD, VV, VV, VV, 0, bhead, 1);
    loss_row_k<<<ROWS, 256>>>(out, tgt, rl);
    if ((size_t)out_size >= NL + 1) {
        loss_final_k<<<1, 256>>>(rl, out + NL);
        size_t tail = (size_t)out_size - (NL + 1);
        if (tail > 0)
            fill0_k<<<(int)((tail + 255) / 256), 256>>>(out + NL + 1, tail);
    }
}

// round 15
// speedup vs baseline: 1.0641x; 1.0641x over previous
#include <cuda_runtime.h>
#include <math.h>
#include <stdint.h>
#include <cuda_fp16.h>

// Problem constants
#define BSZ 4
#define TT 1024
#define DD 768
#define HH 12
#define KH 64
#define LL 6
#define VV 32000
#define FF 3072
#define HD 9216
#define ROWS (BSZ*TT)  // 4096
#define L2E 1.44269504088896340736f

// ---------------- scratch ------------------------------------------------------
__device__ float  g_x[(size_t)ROWS*DD];          // residual (fp32)
__device__ __half g_h[(size_t)ROWS*DD];          // ln output
__device__ __half g_qk[(size_t)2*ROWS*DD];       // q then k
__device__ __half g_v[(size_t)ROWS*HD];
__device__ __half g_o[(size_t)ROWS*HD];
__device__ __half g_p[(size_t)BSZ*HH*TT*TT];     // scores/probs
__device__ __half g_f[(size_t)ROWS*FF];
__device__ float  g_sk[(size_t)2*ROWS*DD];       // split-K fp32 partials
__device__ float  g_rl[ROWS];

// half weight cache
#define WQ_SZ  3538944
#define WV_SZ  42467328
#define WP_SZ  42467328
#define W1_SZ  14155776
#define WH_SZ  24576000
#define O_WQ   0
#define O_WK   (O_WQ + WQ_SZ)
#define O_WV   (O_WK + WQ_SZ)
#define O_WP   (O_WV + WV_SZ)
#define O_W1   (O_WP + WP_SZ)
#define O_W2   (O_W1 + W1_SZ)
#define O_WH   (O_W2 + W1_SZ)
#define WC_TOTAL (O_WH + WH_SZ)
__device__ __half g_wc[(size_t)WC_TOTAL];

// ---------------- helpers ------------------------------------------------------
// two exp2's through one MUFU op (f16x2)
__device__ __forceinline__ float2 exp2_pair(float a, float b) {
    __half2 p = __floats2half2_rn(a, b);
    __half2 e = h2exp2(p);
    return __half22float2(e);
}

__device__ __forceinline__ void mma_f16(float c[4], const uint32_t a[4], uint32_t b0, uint32_t b1) {
    asm volatile(
        "mma.sync.aligned.m16n8k16.row.col.f32.f16.f16.f32 "
        "{%0,%1,%2,%3},{%4,%5,%6,%7},{%8,%9},{%0,%1,%2,%3};"
        : "+f"(c[0]), "+f"(c[1]), "+f"(c[2]), "+f"(c[3])
        : "r"(a[0]), "r"(a[1]), "r"(a[2]), "r"(a[3]), "r"(b0), "r"(b1));
}
__device__ __forceinline__ void ldsm4(uint32_t r[4], uint32_t addr) {
    asm volatile("ldmatrix.sync.aligned.m8n8.x4.shared.b16 {%0,%1,%2,%3}, [%4];"
        : "=r"(r[0]), "=r"(r[1]), "=r"(r[2]), "=r"(r[3]) : "r"(addr));
}
__device__ __forceinline__ void ldsm4t(uint32_t r[4], uint32_t addr) {
    asm volatile("ldmatrix.sync.aligned.m8n8.x4.trans.shared.b16 {%0,%1,%2,%3}, [%4];"
        : "=r"(r[0]), "=r"(r[1]), "=r"(r[2]), "=r"(r[3]) : "r"(addr));
}
#define CP16(dst, src) asm volatile("cp.async.cg.shared.global [%0], [%1], 16;" :: "r"(dst), "l"(src))
#define CP_COMMIT() asm volatile("cp.async.commit_group;")
#define CP_WAIT2() asm volatile("cp.async.wait_group 2;")
#define CP_WAIT0() asm volatile("cp.async.wait_group 0;")

// ---------------- small kernels ------------------------------------------------
__global__ void cvt_k(const float4* __restrict__ s, uint2* __restrict__ d, size_t n4) {
    size_t i = (size_t)blockIdx.x * blockDim.x + threadIdx.x;
    size_t stride = (size_t)gridDim.x * blockDim.x;
    for (; i < n4; i += stride) {
        float4 v = s[i];
        __half2 h0 = __floats2half2_rn(v.x, v.y);
        __half2 h1 = __floats2half2_rn(v.z, v.w);
        uint2 o;
        o.x = *(uint32_t*)&h0;
        o.y = *(uint32_t*)&h1;
        d[i] = o;
    }
}

__global__ void embed_k(const int* __restrict__ ids, const float* __restrict__ tok,
                        const float* __restrict__ pos, float* __restrict__ x) {
    int row = blockIdx.x;
    int t = row % TT;
    int id = ids[row];
    const float* te = tok + (size_t)id * DD;
    const float* pe = pos + (size_t)t * DD;
    float* xr = x + (size_t)row * DD;
    for (int i = threadIdx.x; i < DD; i += blockDim.x)
        xr[i] = te[i] + pe[i];
}

// warp-per-row layernorm; fp32 in, half out
__global__ __launch_bounds__(256)
void ln_k(const float* __restrict__ x, __half* __restrict__ y,
          const float* __restrict__ g, const float* __restrict__ b) {
    int wid = threadIdx.x >> 5, lane = threadIdx.x & 31;
    int row = blockIdx.x * 8 + wid;
    const float* xr = x + (size_t)row * DD;
    float4 vv[6];
    float sum = 0.f, sq = 0.f;
#pragma unroll
    for (int i = 0; i < 6; i++) {
        vv[i] = *(const float4*)(xr + i * 128 + lane * 4);
        sum += vv[i].x + vv[i].y + vv[i].z + vv[i].w;
        sq  += vv[i].x*vv[i].x + vv[i].y*vv[i].y + vv[i].z*vv[i].z + vv[i].w*vv[i].w;
    }
#pragma unroll
    for (int o = 16; o; o >>= 1) {
        sum += __shfl_xor_sync(~0u, sum, o);
        sq  += __shfl_xor_sync(~0u, sq, o);
    }
    float mu = sum * (1.0f / DD);
    float var = sq * (1.0f / DD) - mu * mu;
    float rstd = rsqrtf(var + 1e-5f);
    __half* yr = y + (size_t)row * DD;
#pragma unroll
    for (int i = 0; i < 6; i++) {
        int c = i * 128 + lane * 4;
        float4 gg = *(const float4*)(g + c);
        float4 bb = *(const float4*)(b + c);
        __half2 h0 = __floats2half2_rn((vv[i].x - mu) * rstd * gg.x + bb.x,
                                       (vv[i].y - mu) * rstd * gg.y + bb.y);
        __half2 h1 = __floats2half2_rn((vv[i].z - mu) * rstd * gg.z + bb.z,
                                       (vv[i].w - mu) * rstd * gg.w + bb.w);
        uint2 o;
        o.x = *(uint32_t*)&h0; o.y = *(uint32_t*)&h1;
        *(uint2*)(yr + c) = o;
    }
}

// fused split-K combine + layernorm: x += s0+s1+bias; y = LN(x)
__global__ __launch_bounds__(256)
void addskln_k(const float4* __restrict__ s0, const float4* __restrict__ s1,
               const float* __restrict__ bias, float4* __restrict__ x,
               const float* __restrict__ g, const float* __restrict__ b,
               __half* __restrict__ y) {
    int wid = threadIdx.x >> 5, lane = threadIdx.x & 31;
    int row = blockIdx.x * 8 + wid;
    size_t b4 = (size_t)row * (DD / 4);
    float4 vv[6];
    float sum = 0.f, sq = 0.f;
#pragma unroll
    for (int i = 0; i < 6; i++) {
        int c4 = i * 32 + lane;
        float4 a = s0[b4 + c4], bb = s1[b4 + c4], c = x[b4 + c4];
        float4 bi = *(const float4*)(bias + c4 * 4);
        c.x += a.x + bb.x + bi.x;
        c.y += a.y + bb.y + bi.y;
        c.z += a.z + bb.z + bi.z;
        c.w += a.w + bb.w + bi.w;
        x[b4 + c4] = c;
        vv[i] = c;
        sum += c.x + c.y + c.z + c.w;
        sq  += c.x*c.x + c.y*c.y + c.z*c.z + c.w*c.w;
    }
#pragma unroll
    for (int o = 16; o; o >>= 1) {
        sum += __shfl_xor_sync(~0u, sum, o);
        sq  += __shfl_xor_sync(~0u, sq, o);
    }
    float mu = sum * (1.0f / DD);
    float var = sq * (1.0f / DD) - mu * mu;
    float rstd = rsqrtf(var + 1e-5f);
    __half* yr = y + (size_t)row * DD;
#pragma unroll
    for (int i = 0; i < 6; i++) {
        int c = i * 128 + lane * 4;
        float4 gg = *(const float4*)(g + c);
        float4 bb = *(const float4*)(b + c);
        __half2 h0 = __floats2half2_rn((vv[i].x - mu) * rstd * gg.x + bb.x,
                                       (vv[i].y - mu) * rstd * gg.y + bb.y);
        __half2 h1 = __floats2half2_rn((vv[i].z - mu) * rstd * gg.z + bb.z,
                                       (vv[i].w - mu) * rstd * gg.w + bb.w);
        uint2 o;
        o.x = *(uint32_t*)&h0; o.y = *(uint32_t*)&h1;
        *(uint2*)(yr + c) = o;
    }
}

// ---------------- fp16 tensor-core GEMM (cp.async 4-stage, BK=32) --------------
// C[M,N] (+)= A[M,K]*B[K,N]; B head-blocked: (k,j) at B + (j/Nh)*hstride + k*ldb + j%Nh
// flags: 1 bias, 2 relu, 4 accumulate(fp32 C), 8 causal-K, 32 store-half
#define AP 40                     // halves per A smem row
#define ABYTES (128*AP*2)         // 10240
#define BP 136                    // halves per B smem row
#define BBYTES (32*BP*2)          // 8704
#define STGB (ABYTES+BBYTES)      // 18944
#define NSTG 4
#define GSMEM (NSTG*STGB)         // 75776
__global__ __launch_bounds__(256, 2)
void gemm_hc(const __half* __restrict__ A, const __half* __restrict__ Bm,
             void* __restrict__ Cv,
             int K, int lda, int ldb, int ldc,
             int Nh, size_t hstride,
             const float* __restrict__ bias, int flags,
             int batchH,
             size_t aOuter, size_t aInner,
             size_t bOuter, size_t bInner,
             size_t cOuter, size_t cInner) {
    extern __shared__ __align__(16) char smem[];
    int z = blockIdx.z;
    int zo = z / batchH, zi = z - zo * batchH;
    A  += zo * aOuter + zi * aInner;
    Bm += zo * bOuter + zi * bInner;
    const size_t cOff = (size_t)zo * cOuter + (size_t)zi * cInner;

    const int tid  = threadIdx.x;
    const int lane = tid & 31;
    const int warp = tid >> 5;
    const int wm = warp >> 2;       // 0..1
    const int wn = warp & 3;        // 0..3
    const int m0 = blockIdx.y * 128;
    const int n0 = blockIdx.x * 128;

    int Kc = K;
    if (flags & 8) { int ke = (blockIdx.y + 1) * 128; if (ke < Kc) Kc = ke; }
    const int steps = Kc >> 5;      // BK = 32

    const int ar0 = tid >> 2,  ac8 = (tid & 3);
    const int br0 = tid >> 4,  bc8 = (tid & 15);
    const __half* aP0 = A + (size_t)(m0 + ar0) * lda + ac8 * 8;
    const __half* aP1 = A + (size_t)(m0 + ar0 + 64) * lda + ac8 * 8;
    const int gcol = n0 + bc8 * 8;
    const __half* bPB = Bm + (size_t)(gcol / Nh) * hstride + (size_t)(gcol % Nh);

    const uint32_t base = (uint32_t)__cvta_generic_to_shared(smem);
    const uint32_t aD0 = base + (uint32_t)(ar0 * 80 + ac8 * 16);
    const uint32_t aD1 = aD0 + 64 * 80;
    const uint32_t bD0 = base + (uint32_t)(ABYTES + br0 * 272 + bc8 * 16);
    const uint32_t bD1 = bD0 + 16 * 272;

    float acc[4][4][4];
#pragma unroll
    for (int mt = 0; mt < 4; mt++)
#pragma unroll
        for (int nt = 0; nt < 4; nt++)
#pragma unroll
            for (int i = 0; i < 4; i++) acc[mt][nt][i] = 0.f;

    const uint32_t aF = base + (uint32_t)(((wm * 64 + (lane & 15)) * AP + (lane >> 4) * 8) * 2);
    const uint32_t bF = base + (uint32_t)(ABYTES +
        (((lane & 7) + ((lane >> 3) & 1) * 8) * BP + wn * 32 + (lane >> 4) * 8) * 2);

#pragma unroll
    for (int pt = 0; pt < NSTG - 1; pt++) {
        if (pt < steps) {
            const uint32_t so = (uint32_t)(pt * STGB);
            const int k0 = pt << 5;
            CP16(aD0 + so, aP0 + k0);
            CP16(aD1 + so, aP1 + k0);
            CP16(bD0 + so, bPB + (size_t)(k0 + br0) * ldb);
            CP16(bD1 + so, bPB + (size_t)(k0 + br0 + 16) * ldb);
        }
        CP_COMMIT();
    }

    int stg = 0;
    for (int s = 0; s < steps; s++) {
        CP_WAIT2();
        __syncthreads();

        {
            const int nt_ = s + NSTG - 1;
            if (nt_ < steps) {
                int ns = stg + NSTG - 1; if (ns >= NSTG) ns -= NSTG;
                const uint32_t so = (uint32_t)(ns * STGB);
                const int k0 = nt_ << 5;
                CP16(aD0 + so, aP0 + k0);
                CP16(aD1 + so, aP1 + k0);
                CP16(bD0 + so, bPB + (size_t)(k0 + br0) * ldb);
                CP16(bD1 + so, bPB + (size_t)(k0 + br0 + 16) * ldb);
            }
            CP_COMMIT();
        }

        const uint32_t aS = aF + (uint32_t)(stg * STGB);
        const uint32_t bS = bF + (uint32_t)(stg * STGB);
#pragma unroll
        for (int ks = 0; ks < 2; ks++) {
            uint32_t af[4][4];
#pragma unroll
            for (int mt = 0; mt < 4; mt++)
                ldsm4(af[mt], aS + (uint32_t)(mt * 16 * AP * 2 + ks * 32));
            uint32_t bf[2][4];
            ldsm4t(bf[0], bS + (uint32_t)(ks * 16 * BP * 2));
            ldsm4t(bf[1], bS + (uint32_t)(ks * 16 * BP * 2 + 32));
#pragma unroll
            for (int nt = 0; nt < 4; nt++) {
                uint32_t b0 = bf[nt >> 1][(nt & 1) * 2];
                uint32_t b1 = bf[nt >> 1][(nt & 1) * 2 + 1];
#pragma unroll
                for (int mt = 0; mt < 4; mt++)
                    mma_f16(acc[mt][nt], af[mt], b0, b1);
            }
        }
        stg++; if (stg >= NSTG) stg = 0;
    }

    // epilogue
#pragma unroll
    for (int mt = 0; mt < 4; mt++) {
        const int row = m0 + wm * 64 + mt * 16 + (lane >> 2);
#pragma unroll
        for (int nt = 0; nt < 4; nt++) {
            const int col = n0 + wn * 32 + nt * 8 + (lane & 3) * 2;
            float2 bi = make_float2(0.f, 0.f);
            if (flags & 1) bi = *(const float2*)(bias + col);
            float2 v0 = make_float2(acc[mt][nt][0] + bi.x, acc[mt][nt][1] + bi.y);
            float2 v1 = make_float2(acc[mt][nt][2] + bi.x, acc[mt][nt][3] + bi.y);
            if (flags & 2) {
                v0.x = fmaxf(v0.x, 0.f); v0.y = fmaxf(v0.y, 0.f);
                v1.x = fmaxf(v1.x, 0.f); v1.y = fmaxf(v1.y, 0.f);
            }
            if (flags & 32) {
                __half* Ch = (__half*)Cv + cOff;
                __half2 h0 = __floats2half2_rn(v0.x, v0.y);
                __half2 h1 = __floats2half2_rn(v1.x, v1.y);
                *(__half2*)(Ch + (size_t)row * ldc + col) = h0;
                *(__half2*)(Ch + (size_t)(row + 8) * ldc + col) = h1;
            } else {
                float* Cf = (float*)Cv + cOff;
                float* c0 = Cf + (size_t)row * ldc + col;
                float* c1 = Cf + (size_t)(row + 8) * ldc + col;
                if (flags & 4) {
                    float2 o0 = *(float2*)c0, o1 = *(float2*)c1;
                    v0.x += o0.x; v0.y += o0.y; v1.x += o1.x; v1.y += o1.y;
                }
                *(float2*)c0 = v0;
                *(float2*)c1 = v1;
            }
        }
    }
}

// ---------------- attention scores (fp16 tensor cores) --------------------------
#define QP 72
#define QBYTES (128*QP*2)      // 18432
#define SSMEM (2*QBYTES)       // 36864
__global__ __launch_bounds__(256, 2)
void score_tc(const __half* __restrict__ q, const __half* __restrict__ k,
              __half* __restrict__ p) {
    extern __shared__ __align__(16) char ss[];
    const int z = blockIdx.z;
    const int b = z / HH, h = z - b * HH;
    const int m0 = blockIdx.y * 128;
    const int n0 = blockIdx.x * 128;
    if (n0 > m0 + 127) return;

    const int tid  = threadIdx.x;
    const int lane = tid & 31;
    const int warp = tid >> 5;
    const int wm = warp >> 2;
    const int wn = warp & 3;

    const __half* qb = q + ((size_t)(b * TT + m0)) * DD + h * KH;
    const __half* kb = k + ((size_t)(b * TT + n0)) * DD + h * KH;

    const uint32_t base = (uint32_t)__cvta_generic_to_shared(ss);
#pragma unroll
    for (int i = 0; i < 4; i++) {
        int c = tid + i * 256;
        int row = c >> 3;
        int cg = c & 7;
        CP16(base + (uint32_t)(row * 144 + cg * 16), qb + (size_t)row * DD + cg * 8);
        CP16(base + (uint32_t)(QBYTES + row * 144 + cg * 16), kb + (size_t)row * DD + cg * 8);
    }
    CP_COMMIT();
    CP_WAIT0();
    __syncthreads();

    float acc[4][4][4];
#pragma unroll
    for (int mt = 0; mt < 4; mt++)
#pragma unroll
        for (int nt = 0; nt < 4; nt++)
#pragma unroll
            for (int i = 0; i < 4; i++) acc[mt][nt][i] = 0.f;

    const uint32_t qF = base + (uint32_t)(((wm * 64 + (lane & 15)) * QP + (lane >> 4) * 8) * 2);
    const uint32_t kF = base + (uint32_t)(QBYTES +
        ((wn * 32 + (lane & 7) + (lane >> 4) * 8) * QP + ((lane >> 3) & 1) * 8) * 2);

#pragma unroll
    for (int ks = 0; ks < 4; ks++) {
        uint32_t af[4][4];
#pragma unroll
        for (int mt = 0; mt < 4; mt++)
            ldsm4(af[mt], qF + (uint32_t)(mt * 16 * QP * 2 + ks * 32));
        uint32_t bf[2][4];
        ldsm4(bf[0], kF + (uint32_t)(ks * 32));
        ldsm4(bf[1], kF + (uint32_t)(16 * QP * 2 + ks * 32));
#pragma unroll
        for (int nt = 0; nt < 4; nt++) {
            uint32_t b0 = bf[nt >> 1][(nt & 1) * 2];
            uint32_t b1 = bf[nt >> 1][(nt & 1) * 2 + 1];
#pragma unroll
            for (int mt = 0; mt < 4; mt++)
                mma_f16(acc[mt][nt], af[mt], b0, b1);
        }
    }

    __half* pz = p + (size_t)z * TT * TT;
#pragma unroll
    for (int mt = 0; mt < 4; mt++) {
        const int row = m0 + wm * 64 + mt * 16 + (lane >> 2);
#pragma unroll
        for (int nt = 0; nt < 4; nt++) {
            const int col = n0 + wn * 32 + nt * 8 + (lane & 3) * 2;
            __half2 h0 = __floats2half2_rn(acc[mt][nt][0] * 0.125f, acc[mt][nt][1] * 0.125f);
            __half2 h1 = __floats2half2_rn(acc[mt][nt][2] * 0.125f, acc[mt][nt][3] * 0.125f);
            *(__half2*)(pz + (size_t)row * TT + col) = h0;
            *(__half2*)(pz + (size_t)(row + 8) * TT + col) = h1;
        }
    }
}

// ---------------- causal softmax: one warp per row (half in/out) ----------------
__global__ __launch_bounds__(256)
void attn_sm(__half* __restrict__ p) {
    const int wid = threadIdx.x >> 5, lane = threadIdx.x & 31;
    const int t = blockIdx.x * 8 + wid;
    const int h = blockIdx.y, b = blockIdx.z;
    __half* row = p + ((size_t)((b * HH + h) * TT + t)) * TT;
    const int valid = t + 1;
    const int nj = (t >> 7) + 1;

    float4 v[8];
    float m = -INFINITY;
#pragma unroll
    for (int j = 0; j < 8; j++) {
        if (j < nj) {
            int c0 = j * 128 + lane * 4;
            uint2 u = *(const uint2*)(row + c0);
            float2 f0 = __half22float2(*(__half2*)&u.x);
            float2 f1 = __half22float2(*(__half2*)&u.y);
            float4 val;
            val.x = (c0 + 0 < valid) ? f0.x : -INFINITY;
            val.y = (c0 + 1 < valid) ? f0.y : -INFINITY;
            val.z = (c0 + 2 < valid) ? f1.x : -INFINITY;
            val.w = (c0 + 3 < valid) ? f1.y : -INFINITY;
            v[j] = val;
            m = fmaxf(m, fmaxf(fmaxf(val.x, val.y), fmaxf(val.z, val.w)));
        }
    }
#pragma unroll
    for (int o = 16; o; o >>= 1) m = fmaxf(m, __shfl_xor_sync(~0u, m, o));

    float sum = 0.f;
#pragma unroll
    for (int j = 0; j < 8; j++) {
        if (j < nj) {
            float2 e0 = exp2_pair((v[j].x - m) * L2E, (v[j].y - m) * L2E);
            float2 e1 = exp2_pair((v[j].z - m) * L2E, (v[j].w - m) * L2E);
            v[j] = make_float4(e0.x, e0.y, e1.x, e1.y);
            sum += e0.x + e0.y + e1.x + e1.y;
        }
    }
#pragma unroll
    for (int o = 16; o; o >>= 1) sum += __shfl_xor_sync(~0u, sum, o);
    float inv = 1.f / sum;
#pragma unroll
    for (int j = 0; j < 8; j++) {
        if (j < nj) {
            int c0 = j * 128 + lane * 4;
            __half2 h0 = __floats2half2_rn(v[j].x * inv, v[j].y * inv);
            __half2 h1 = __floats2half2_rn(v[j].z * inv, v[j].w * inv);
            uint2 u;
            u.x = *(uint32_t*)&h0; u.y = *(uint32_t*)&h1;
            *(uint2*)(row + c0) = u;
        }
    }
}

// ---------------- loss ----------------------------------------------------------
__global__ void loss_row_k(const float* __restrict__ logits, const int* __restrict__ tgt,
                           float* __restrict__ rl) {
    int row = blockIdx.x, tid = threadIdx.x;
    const float* lr = logits + (size_t)row * VV;
    __shared__ float red[256];
    float m = -INFINITY;
    for (int i = tid * 2; i < VV; i += 512) {
        float2 v = *(const float2*)(lr + i);
        m = fmaxf(m, fmaxf(v.x, v.y));
    }
    red[tid] = m; __syncthreads();
    for (int s = 128; s > 0; s >>= 1) { if (tid < s) red[tid] = fmaxf(red[tid], red[tid + s]); __syncthreads(); }
    m = red[0]; __syncthreads();
    float sum = 0.f;
    for (int i = tid * 2; i < VV; i += 512) {
        float2 v = *(const float2*)(lr + i);
        float2 e = exp2_pair((v.x - m) * L2E, (v.y - m) * L2E);
        sum += e.x + e.y;
    }
    red[tid] = sum; __syncthreads();
    for (int s = 128; s > 0; s >>= 1) { if (tid < s) red[tid] += red[tid + s]; __syncthreads(); }
    if (tid == 0) {
        float lse = m + logf(red[0]);
        rl[row] = lse - lr[tgt[row]];
    }
}

__global__ void loss_final_k(const float* __restrict__ rl, float* __restrict__ out) {
    __shared__ float red[256];
    int tid = threadIdx.x;
    float s = 0.f;
    for (int i = tid; i < ROWS; i += 256) s += rl[i];
    red[tid] = s; __syncthreads();
    for (int k = 128; k > 0; k >>= 1) { if (tid < k) red[tid] += red[tid + k]; __syncthreads(); }
    if (tid == 0) out[0] = red[0] * (1.0f / ROWS);
}

__global__ void fill0_k(float* p, size_t n) {
    size_t i = (size_t)blockIdx.x * blockDim.x + threadIdx.x;
    if (i < n) p[i] = 0.f;
}

// ---------------- host-side launcher -------------------------------------------
static inline void gemm(const __half* A, const __half* B, void* C,
                        int M, int N, int K, int lda, int ldb, int ldc,
                        int Nh, size_t hs, const float* bias, int flags,
                        int batch = 1, int batchH = 1,
                        size_t aO = 0, size_t aI = 0,
                        size_t bO = 0, size_t bI = 0,
                        size_t cO = 0, size_t cI = 0) {
    dim3 grid(N / 128, M / 128, batch);
    gemm_hc<<<grid, 256, GSMEM>>>(A, B, C, K, lda, ldb, ldc, Nh, hs, bias, flags,
                                  batchH, aO, aI, bO, bI, cO, cI);
}

extern "C" void kernel_launch(void* const* d_in, const int* in_sizes, int n_in,
                              void* d_out, int out_size) {
    const int*   ids   = (const int*)d_in[0];
    const int*   tgt   = (const int*)d_in[1];
    const float* tok   = (const float*)d_in[2];
    const float* pos   = (const float*)d_in[3];
    const float* Wq_i  = (const float*)d_in[4];
    const float* Wk_i  = (const float*)d_in[5];
    const float* Wv_i  = (const float*)d_in[6];
    const float* Wp_i  = (const float*)d_in[7];
    const float* bproj = (const float*)d_in[8];
    const float* ln1g  = (const float*)d_in[9];
    const float* ln1b  = (const float*)d_in[10];
    const float* ln2g  = (const float*)d_in[11];
    const float* ln2b  = (const float*)d_in[12];
    const float* W1_i  = (const float*)d_in[13];
    const float* b1    = (const float*)d_in[14];
    const float* W2_i  = (const float*)d_in[15];
    const float* b2    = (const float*)d_in[16];
    const float* lnfg  = (const float*)d_in[17];
    const float* lnfb  = (const float*)d_in[18];
    const float* Wh_i  = (const float*)d_in[19];
    const float* bhead = (const float*)d_in[20];

    float *x, *sk, *rl;
    __half *h, *qk, *v, *o, *p, *f, *wc;
    cudaGetSymbolAddress((void**)&x, g_x);
    cudaGetSymbolAddress((void**)&h, g_h);
    cudaGetSymbolAddress((void**)&qk, g_qk);
    cudaGetSymbolAddress((void**)&v, g_v);
    cudaGetSymbolAddress((void**)&o, g_o);
    cudaGetSymbolAddress((void**)&p, g_p);
    cudaGetSymbolAddress((void**)&f, g_f);
    cudaGetSymbolAddress((void**)&sk, g_sk);
    cudaGetSymbolAddress((void**)&rl, g_rl);
    cudaGetSymbolAddress((void**)&wc, g_wc);

    static bool attrSet = false;
    if (!attrSet) {
        cudaFuncSetAttribute(gemm_hc, cudaFuncAttributeMaxDynamicSharedMemorySize, GSMEM);
        cudaFuncSetAttribute(score_tc, cudaFuncAttributeMaxDynamicSharedMemorySize, SSMEM);
        attrSet = true;
    }

    __half* Wq = wc + O_WQ;  __half* Wk = wc + O_WK;  __half* Wv = wc + O_WV;
    __half* Wp = wc + O_WP;  __half* W1 = wc + O_W1;  __half* W2 = wc + O_W2;
    __half* Wh = wc + O_WH;
    __half* q = qk;
    __half* k = qk + (size_t)ROWS * DD;

    float* out = (float*)d_out;
    const size_t NL = (size_t)ROWS * VV;

    embed_k<<<ROWS, 256>>>(ids, tok, pos, x);
    cvt_k<<<1024, 256>>>((const float4*)Wq_i, (uint2*)Wq, (size_t)WQ_SZ / 4);
    cvt_k<<<1024, 256>>>((const float4*)Wk_i, (uint2*)Wk, (size_t)WQ_SZ / 4);
    ln_k<<<ROWS / 8, 256>>>(x, h, ln1g, ln1b);
    cvt_k<<<2048, 256>>>((const float4*)Wv_i, (uint2*)Wv, (size_t)WV_SZ / 4);
    // merged q/k projection for layer 0
    gemm(h, Wq, q, ROWS, DD, DD, DD, KH, DD, KH, (size_t)DD * KH, nullptr, 32,
         2, 1, 0, 0, (size_t)WQ_SZ, 0, (size_t)ROWS * DD, 0);
    cvt_k<<<2048, 256>>>((const float4*)Wp_i, (uint2*)Wp, (size_t)WP_SZ / 4);
    cvt_k<<<1024, 256>>>((const float4*)W1_i, (uint2*)W1, (size_t)W1_SZ / 4);
    cvt_k<<<1024, 256>>>((const float4*)W2_i, (uint2*)W2, (size_t)W1_SZ / 4);
    cvt_k<<<2048, 256>>>((const float4*)Wh_i, (uint2*)Wh, (size_t)WH_SZ / 4);

    for (int l = 0; l < LL; l++) {
        if (l > 0) {
            gemm(h, Wq + (size_t)l * HH * DD * KH, q, ROWS, DD, DD, DD, KH, DD,
                 KH, (size_t)DD * KH, nullptr, 32,
                 2, 1, 0, 0, (size_t)WQ_SZ, 0, (size_t)ROWS * DD, 0);
        }
        gemm(h, Wv + (size_t)l * HH * DD * DD, v, ROWS, HD, DD, DD, DD, HD,
             DD, (size_t)DD * DD, nullptr, 32);
        {
            dim3 grid(TT / 128, TT / 128, BSZ * HH);
            score_tc<<<grid, 256, SSMEM>>>(q, k, p);
            dim3 grid2(TT / 8, HH, BSZ);
            attn_sm<<<grid2, 256>>>(p);
        }
        gemm(p, v, o, TT, DD, TT, TT, HD, HD, DD, 0, nullptr, 8 | 32,
             BSZ * HH, HH,
             (size_t)HH * TT * TT, (size_t)TT * TT,
             (size_t)TT * HD, (size_t)DD,
             (size_t)TT * HD, (size_t)DD);
        // proj: split-K x2 (fp32 partials), fused combine + ln2 -> h
        gemm(o, Wp + (size_t)l * HD * DD, sk, ROWS, DD, HD / 2, HD, DD, DD,
             DD, 0, nullptr, 0,
             2, 1, (size_t)(HD / 2), 0, (size_t)(HD / 2) * DD, 0, (size_t)ROWS * DD, 0);
        addskln_k<<<ROWS / 8, 256>>>((const float4*)sk,
                                     (const float4*)(sk + (size_t)ROWS * DD),
                                     bproj + l * DD, (float4*)x,
                                     ln2g + l * DD, ln2b + l * DD, h);
        gemm(h, W1 + (size_t)l * DD * FF, f, ROWS, FF, DD, DD, FF, FF,
             FF, 0, b1 + l * FF, 1 | 2 | 32);
        gemm(f, W2 + (size_t)l * FF * DD, sk, ROWS, DD, FF / 2, FF, DD, DD,
             DD, 0, nullptr, 0,
             2, 1, (size_t)(FF / 2), 0, (size_t)(FF / 2) * DD, 0, (size_t)ROWS * DD, 0);
        // fused combine + (ln1 of next layer, or final ln) -> h
        const float* ng = (l + 1 < LL) ? (ln1g + (l + 1) * DD) : lnfg;
        const float* nb = (l + 1 < LL) ? (ln1b + (l + 1) * DD) : lnfb;
        addskln_k<<<ROWS / 8, 256>>>((const float4*)sk,
                                     (const float4*)(sk + (size_t)ROWS * DD),
                                     b2 + l * DD, (float4*)x, ng, nb, h);
    }

    gemm(h, Wh, out, ROWS, VV, DD, DD, VV, VV, VV, 0, bhead, 1);
    loss_row_k<<<ROWS, 256>>>(out, tgt, rl);
    if ((size_t)out_size >= NL + 1) {
        loss_final_k<<<1, 256>>>(rl, out + NL);
        size_t tail = (size_t)out_size - (NL + 1);
        if (tail > 0)
            fill0_k<<<(int)((tail + 255) / 256), 256>>>(out + NL + 1, tail);
    }
}

// round 17
// speedup vs baseline: 1.0764x; 1.0115x over previous
#include <cuda_runtime.h>
#include <math.h>
#include <stdint.h>
#include <cuda_fp16.h>

// Problem constants
#define BSZ 4
#define TT 1024
#define DD 768
#define HH 12
#define KH 64
#define LL 6
#define VV 32000
#define FF 3072
#define HD 9216
#define ROWS (BSZ*TT)  // 4096
#define L2E 1.44269504088896340736f

// ---------------- scratch ------------------------------------------------------
__device__ float  g_x[(size_t)ROWS*DD];          // residual (fp32)
__device__ __half g_h[(size_t)ROWS*DD];          // ln output
__device__ __half g_qk[(size_t)2*ROWS*DD];       // q then k
__device__ __half g_v[(size_t)ROWS*HD];
__device__ __half g_o[(size_t)ROWS*HD];
__device__ __half g_p[(size_t)BSZ*HH*TT*TT];     // scores/probs
__device__ __half g_f[(size_t)ROWS*FF];
__device__ float  g_sk[(size_t)2*ROWS*DD];       // split-K fp32 partials
__device__ float  g_rl[ROWS];

// half weight cache
#define WQ_SZ  3538944
#define WV_SZ  42467328
#define WP_SZ  42467328
#define W1_SZ  14155776
#define WH_SZ  24576000
#define O_WQ   0
#define O_WK   (O_WQ + WQ_SZ)
#define O_WV   (O_WK + WQ_SZ)
#define O_WP   (O_WV + WV_SZ)
#define O_W1   (O_WP + WP_SZ)
#define O_W2   (O_W1 + W1_SZ)
#define O_WH   (O_W2 + W1_SZ)
#define WC_TOTAL (O_WH + WH_SZ)
__device__ __half g_wc[(size_t)WC_TOTAL];

// ---------------- helpers ------------------------------------------------------
// two exp2's through one MUFU op (f16x2)
__device__ __forceinline__ float2 exp2_pair(float a, float b) {
    __half2 p = __floats2half2_rn(a, b);
    __half2 e = h2exp2(p);
    return __half22float2(e);
}

__device__ __forceinline__ void mma_f16(float c[4], const uint32_t a[4], uint32_t b0, uint32_t b1) {
    asm volatile(
        "mma.sync.aligned.m16n8k16.row.col.f32.f16.f16.f32 "
        "{%0,%1,%2,%3},{%4,%5,%6,%7},{%8,%9},{%0,%1,%2,%3};"
        : "+f"(c[0]), "+f"(c[1]), "+f"(c[2]), "+f"(c[3])
        : "r"(a[0]), "r"(a[1]), "r"(a[2]), "r"(a[3]), "r"(b0), "r"(b1));
}
__device__ __forceinline__ void ldsm4(uint32_t r[4], uint32_t addr) {
    asm volatile("ldmatrix.sync.aligned.m8n8.x4.shared.b16 {%0,%1,%2,%3}, [%4];"
        : "=r"(r[0]), "=r"(r[1]), "=r"(r[2]), "=r"(r[3]) : "r"(addr));
}
__device__ __forceinline__ void ldsm4t(uint32_t r[4], uint32_t addr) {
    asm volatile("ldmatrix.sync.aligned.m8n8.x4.trans.shared.b16 {%0,%1,%2,%3}, [%4];"
        : "=r"(r[0]), "=r"(r[1]), "=r"(r[2]), "=r"(r[3]) : "r"(addr));
}
#define CP16(dst, src) asm volatile("cp.async.cg.shared.global [%0], [%1], 16;" :: "r"(dst), "l"(src))
#define CP_COMMIT() asm volatile("cp.async.commit_group;")
#define CP_WAIT2() asm volatile("cp.async.wait_group 2;")
#define CP_WAIT0() asm volatile("cp.async.wait_group 0;")

// ---------------- small kernels ------------------------------------------------
__global__ void cvt_k(const float4* __restrict__ s, uint2* __restrict__ d, size_t n4) {
    size_t i = (size_t)blockIdx.x * blockDim.x + threadIdx.x;
    size_t stride = (size_t)gridDim.x * blockDim.x;
    for (; i < n4; i += stride) {
        float4 v = s[i];
        __half2 h0 = __floats2half2_rn(v.x, v.y);
        __half2 h1 = __floats2half2_rn(v.z, v.w);
        uint2 o;
        o.x = *(uint32_t*)&h0;
        o.y = *(uint32_t*)&h1;
        d[i] = o;
    }
}

__global__ void embed_k(const int* __restrict__ ids, const float* __restrict__ tok,
                        const float* __restrict__ pos, float* __restrict__ x) {
    int row = blockIdx.x;
    int t = row % TT;
    int id = ids[row];
    const float* te = tok + (size_t)id * DD;
    const float* pe = pos + (size_t)t * DD;
    float* xr = x + (size_t)row * DD;
    for (int i = threadIdx.x; i < DD; i += blockDim.x)
        xr[i] = te[i] + pe[i];
}

// warp-per-row layernorm; fp32 in, half out
__global__ __launch_bounds__(256)
void ln_k(const float* __restrict__ x, __half* __restrict__ y,
          const float* __restrict__ g, const float* __restrict__ b) {
    int wid = threadIdx.x >> 5, lane = threadIdx.x & 31;
    int row = blockIdx.x * 8 + wid;
    const float* xr = x + (size_t)row * DD;
    float4 vv[6];
    float sum = 0.f, sq = 0.f;
#pragma unroll
    for (int i = 0; i < 6; i++) {
        vv[i] = *(const float4*)(xr + i * 128 + lane * 4);
        sum += vv[i].x + vv[i].y + vv[i].z + vv[i].w;
        sq  += vv[i].x*vv[i].x + vv[i].y*vv[i].y + vv[i].z*vv[i].z + vv[i].w*vv[i].w;
    }
#pragma unroll
    for (int o = 16; o; o >>= 1) {
        sum += __shfl_xor_sync(~0u, sum, o);
        sq  += __shfl_xor_sync(~0u, sq, o);
    }
    float mu = sum * (1.0f / DD);
    float var = sq * (1.0f / DD) - mu * mu;
    float rstd = rsqrtf(var + 1e-5f);
    __half* yr = y + (size_t)row * DD;
#pragma unroll
    for (int i = 0; i < 6; i++) {
        int c = i * 128 + lane * 4;
        float4 gg = *(const float4*)(g + c);
        float4 bb = *(const float4*)(b + c);
        __half2 h0 = __floats2half2_rn((vv[i].x - mu) * rstd * gg.x + bb.x,
                                       (vv[i].y - mu) * rstd * gg.y + bb.y);
        __half2 h1 = __floats2half2_rn((vv[i].z - mu) * rstd * gg.z + bb.z,
                                       (vv[i].w - mu) * rstd * gg.w + bb.w);
        uint2 o;
        o.x = *(uint32_t*)&h0; o.y = *(uint32_t*)&h1;
        *(uint2*)(yr + c) = o;
    }
}

// fused split-K combine + layernorm: x += s0+s1+bias; y = LN(x)
__global__ __launch_bounds__(256)
void addskln_k(const float4* __restrict__ s0, const float4* __restrict__ s1,
               const float* __restrict__ bias, float4* __restrict__ x,
               const float* __restrict__ g, const float* __restrict__ b,
               __half* __restrict__ y) {
    int wid = threadIdx.x >> 5, lane = threadIdx.x & 31;
    int row = blockIdx.x * 8 + wid;
    size_t b4 = (size_t)row * (DD / 4);
    float4 vv[6];
    float sum = 0.f, sq = 0.f;
#pragma unroll
    for (int i = 0; i < 6; i++) {
        int c4 = i * 32 + lane;
        float4 a = s0[b4 + c4], bb = s1[b4 + c4], c = x[b4 + c4];
        float4 bi = *(const float4*)(bias + c4 * 4);
        c.x += a.x + bb.x + bi.x;
        c.y += a.y + bb.y + bi.y;
        c.z += a.z + bb.z + bi.z;
        c.w += a.w + bb.w + bi.w;
        x[b4 + c4] = c;
        vv[i] = c;
        sum += c.x + c.y + c.z + c.w;
        sq  += c.x*c.x + c.y*c.y + c.z*c.z + c.w*c.w;
    }
#pragma unroll
    for (int o = 16; o; o >>= 1) {
        sum += __shfl_xor_sync(~0u, sum, o);
        sq  += __shfl_xor_sync(~0u, sq, o);
    }
    float mu = sum * (1.0f / DD);
    float var = sq * (1.0f / DD) - mu * mu;
    float rstd = rsqrtf(var + 1e-5f);
    __half* yr = y + (size_t)row * DD;
#pragma unroll
    for (int i = 0; i < 6; i++) {
        int c = i * 128 + lane * 4;
        float4 gg = *(const float4*)(g + c);
        float4 bb = *(const float4*)(b + c);
        __half2 h0 = __floats2half2_rn((vv[i].x - mu) * rstd * gg.x + bb.x,
                                       (vv[i].y - mu) * rstd * gg.y + bb.y);
        __half2 h1 = __floats2half2_rn((vv[i].z - mu) * rstd * gg.z + bb.z,
                                       (vv[i].w - mu) * rstd * gg.w + bb.w);
        uint2 o;
        o.x = *(uint32_t*)&h0; o.y = *(uint32_t*)&h1;
        *(uint2*)(yr + c) = o;
    }
}

// ---------------- fp16 tensor-core GEMM (cp.async 4-stage, BK=32) --------------
// C[M,N] (+)= A[M,K]*B[K,N]; B head-blocked: (k,j) at B + (j/Nh)*hstride + k*ldb + j%Nh
// flags: 1 bias, 2 relu, 4 accumulate(fp32 C), 8 causal-K, 32 store-half
#define AP 40                     // halves per A smem row
#define ABYTES (128*AP*2)         // 10240
#define BP 136                    // halves per B smem row
#define BBYTES (32*BP*2)          // 8704
#define STGB (ABYTES+BBYTES)      // 18944
#define NSTG 4
#define GSMEM (NSTG*STGB)         // 75776
__global__ __launch_bounds__(256, 2)
void gemm_hc(const __half* __restrict__ A, const __half* __restrict__ Bm,
             void* __restrict__ Cv,
             int K, int lda, int ldb, int ldc,
             int Nh, size_t hstride,
             const float* __restrict__ bias, int flags,
             int batchH,
             size_t aOuter, size_t aInner,
             size_t bOuter, size_t bInner,
             size_t cOuter, size_t cInner) {
    extern __shared__ __align__(16) char smem[];
    int z = blockIdx.z;
    int zo = z / batchH, zi = z - zo * batchH;
    A  += zo * aOuter + zi * aInner;
    Bm += zo * bOuter + zi * bInner;
    const size_t cOff = (size_t)zo * cOuter + (size_t)zi * cInner;

    const int tid  = threadIdx.x;
    const int lane = tid & 31;
    const int warp = tid >> 5;
    const int wm = warp >> 2;       // 0..1
    const int wn = warp & 3;        // 0..3
    const int m0 = blockIdx.y * 128;
    const int n0 = blockIdx.x * 128;

    int Kc = K;
    if (flags & 8) { int ke = (blockIdx.y + 1) * 128; if (ke < Kc) Kc = ke; }
    const int steps = Kc >> 5;      // BK = 32

    const int ar0 = tid >> 2,  ac8 = (tid & 3);
    const int br0 = tid >> 4,  bc8 = (tid & 15);
    const __half* aP0 = A + (size_t)(m0 + ar0) * lda + ac8 * 8;
    const __half* aP1 = A + (size_t)(m0 + ar0 + 64) * lda + ac8 * 8;
    const int gcol = n0 + bc8 * 8;
    const __half* bPB = Bm + (size_t)(gcol / Nh) * hstride + (size_t)(gcol % Nh);

    const uint32_t base = (uint32_t)__cvta_generic_to_shared(smem);
    const uint32_t aD0 = base + (uint32_t)(ar0 * 80 + ac8 * 16);
    const uint32_t aD1 = aD0 + 64 * 80;
    const uint32_t bD0 = base + (uint32_t)(ABYTES + br0 * 272 + bc8 * 16);
    const uint32_t bD1 = bD0 + 16 * 272;

    float acc[4][4][4];
#pragma unroll
    for (int mt = 0; mt < 4; mt++)
#pragma unroll
        for (int nt = 0; nt < 4; nt++)
#pragma unroll
            for (int i = 0; i < 4; i++) acc[mt][nt][i] = 0.f;

    const uint32_t aF = base + (uint32_t)(((wm * 64 + (lane & 15)) * AP + (lane >> 4) * 8) * 2);
    const uint32_t bF = base + (uint32_t)(ABYTES +
        (((lane & 7) + ((lane >> 3) & 1) * 8) * BP + wn * 32 + (lane >> 4) * 8) * 2);

#pragma unroll
    for (int pt = 0; pt < NSTG - 1; pt++) {
        if (pt < steps) {
            const uint32_t so = (uint32_t)(pt * STGB);
            const int k0 = pt << 5;
            CP16(aD0 + so, aP0 + k0);
            CP16(aD1 + so, aP1 + k0);
            CP16(bD0 + so, bPB + (size_t)(k0 + br0) * ldb);
            CP16(bD1 + so, bPB + (size_t)(k0 + br0 + 16) * ldb);
        }
        CP_COMMIT();
    }

    int stg = 0;
    for (int s = 0; s < steps; s++) {
        CP_WAIT2();
        __syncthreads();

        {
            const int nt_ = s + NSTG - 1;
            if (nt_ < steps) {
                int ns = stg + NSTG - 1; if (ns >= NSTG) ns -= NSTG;
                const uint32_t so = (uint32_t)(ns * STGB);
                const int k0 = nt_ << 5;
                CP16(aD0 + so, aP0 + k0);
                CP16(aD1 + so, aP1 + k0);
                CP16(bD0 + so, bPB + (size_t)(k0 + br0) * ldb);
                CP16(bD1 + so, bPB + (size_t)(k0 + br0 + 16) * ldb);
            }
            CP_COMMIT();
        }

        const uint32_t aS = aF + (uint32_t)(stg * STGB);
        const uint32_t bS = bF + (uint32_t)(stg * STGB);
#pragma unroll
        for (int ks = 0; ks < 2; ks++) {
            uint32_t af[4][4];
#pragma unroll
            for (int mt = 0; mt < 4; mt++)
                ldsm4(af[mt], aS + (uint32_t)(mt * 16 * AP * 2 + ks * 32));
            uint32_t bf[2][4];
            ldsm4t(bf[0], bS + (uint32_t)(ks * 16 * BP * 2));
            ldsm4t(bf[1], bS + (uint32_t)(ks * 16 * BP * 2 + 32));
#pragma unroll
            for (int nt = 0; nt < 4; nt++) {
                uint32_t b0 = bf[nt >> 1][(nt & 1) * 2];
                uint32_t b1 = bf[nt >> 1][(nt & 1) * 2 + 1];
#pragma unroll
                for (int mt = 0; mt < 4; mt++)
                    mma_f16(acc[mt][nt], af[mt], b0, b1);
            }
        }
        stg++; if (stg >= NSTG) stg = 0;
    }

    // epilogue
#pragma unroll
    for (int mt = 0; mt < 4; mt++) {
        const int row = m0 + wm * 64 + mt * 16 + (lane >> 2);
#pragma unroll
        for (int nt = 0; nt < 4; nt++) {
            const int col = n0 + wn * 32 + nt * 8 + (lane & 3) * 2;
            float2 bi = make_float2(0.f, 0.f);
            if (flags & 1) bi = *(const float2*)(bias + col);
            float2 v0 = make_float2(acc[mt][nt][0] + bi.x, acc[mt][nt][1] + bi.y);
            float2 v1 = make_float2(acc[mt][nt][2] + bi.x, acc[mt][nt][3] + bi.y);
            if (flags & 2) {
                v0.x = fmaxf(v0.x, 0.f); v0.y = fmaxf(v0.y, 0.f);
                v1.x = fmaxf(v1.x, 0.f); v1.y = fmaxf(v1.y, 0.f);
            }
            if (flags & 32) {
                __half* Ch = (__half*)Cv + cOff;
                __half2 h0 = __floats2half2_rn(v0.x, v0.y);
                __half2 h1 = __floats2half2_rn(v1.x, v1.y);
                *(__half2*)(Ch + (size_t)row * ldc + col) = h0;
                *(__half2*)(Ch + (size_t)(row + 8) * ldc + col) = h1;
            } else {
                float* Cf = (float*)Cv + cOff;
                float* c0 = Cf + (size_t)row * ldc + col;
                float* c1 = Cf + (size_t)(row + 8) * ldc + col;
                if (flags & 4) {
                    float2 o0 = *(float2*)c0, o1 = *(float2*)c1;
                    v0.x += o0.x; v0.y += o0.y; v1.x += o1.x; v1.y += o1.y;
                }
                *(float2*)c0 = v0;
                *(float2*)c1 = v1;
            }
        }
    }
}

// ---------------- attention scores (fp16 tensor cores) --------------------------
#define QP 72
#define QBYTES (128*QP*2)      // 18432
#define SSMEM (2*QBYTES)       // 36864
__global__ __launch_bounds__(256, 2)
void score_tc(const __half* __restrict__ q, const __half* __restrict__ k,
              __half* __restrict__ p) {
    extern __shared__ __align__(16) char ss[];
    const int z = blockIdx.z;
    const int b = z / HH, h = z - b * HH;
    const int m0 = blockIdx.y * 128;
    const int n0 = blockIdx.x * 128;
    if (n0 > m0 + 127) return;

    const int tid  = threadIdx.x;
    const int lane = tid & 31;
    const int warp = tid >> 5;
    const int wm = warp >> 2;
    const int wn = warp & 3;

    const __half* qb = q + ((size_t)(b * TT + m0)) * DD + h * KH;
    const __half* kb = k + ((size_t)(b * TT + n0)) * DD + h * KH;

    const uint32_t base = (uint32_t)__cvta_generic_to_shared(ss);
#pragma unroll
    for (int i = 0; i < 4; i++) {
        int c = tid + i * 256;
        int row = c >> 3;
        int cg = c & 7;
        CP16(base + (uint32_t)(row * 144 + cg * 16), qb + (size_t)row * DD + cg * 8);
        CP16(base + (uint32_t)(QBYTES + row * 144 + cg * 16), kb + (size_t)row * DD + cg * 8);
    }
    CP_COMMIT();
    CP_WAIT0();
    __syncthreads();

    float acc[4][4][4];
#pragma unroll
    for (int mt = 0; mt < 4; mt++)
#pragma unroll
        for (int nt = 0; nt < 4; nt++)
#pragma unroll
            for (int i = 0; i < 4; i++) acc[mt][nt][i] = 0.f;

    const uint32_t qF = base + (uint32_t)(((wm * 64 + (lane & 15)) * QP + (lane >> 4) * 8) * 2);
    const uint32_t kF = base + (uint32_t)(QBYTES +
        ((wn * 32 + (lane & 7) + (lane >> 4) * 8) * QP + ((lane >> 3) & 1) * 8) * 2);

#pragma unroll
    for (int ks = 0; ks < 4; ks++) {
        uint32_t af[4][4];
#pragma unroll
        for (int mt = 0; mt < 4; mt++)
            ldsm4(af[mt], qF + (uint32_t)(mt * 16 * QP * 2 + ks * 32));
        uint32_t bf[2][4];
        ldsm4(bf[0], kF + (uint32_t)(ks * 32));
        ldsm4(bf[1], kF + (uint32_t)(16 * QP * 2 + ks * 32));
#pragma unroll
        for (int nt = 0; nt < 4; nt++) {
            uint32_t b0 = bf[nt >> 1][(nt & 1) * 2];
            uint32_t b1 = bf[nt >> 1][(nt & 1) * 2 + 1];
#pragma unroll
            for (int mt = 0; mt < 4; mt++)
                mma_f16(acc[mt][nt], af[mt], b0, b1);
        }
    }

    __half* pz = p + (size_t)z * TT * TT;
#pragma unroll
    for (int mt = 0; mt < 4; mt++) {
        const int row = m0 + wm * 64 + mt * 16 + (lane >> 2);
#pragma unroll
        for (int nt = 0; nt < 4; nt++) {
            const int col = n0 + wn * 32 + nt * 8 + (lane & 3) * 2;
            __half2 h0 = __floats2half2_rn(acc[mt][nt][0] * 0.125f, acc[mt][nt][1] * 0.125f);
            __half2 h1 = __floats2half2_rn(acc[mt][nt][2] * 0.125f, acc[mt][nt][3] * 0.125f);
            *(__half2*)(pz + (size_t)row * TT + col) = h0;
            *(__half2*)(pz + (size_t)(row + 8) * TT + col) = h1;
        }
    }
}

// ---------------- causal softmax: one warp per row (half in/out) ----------------
__global__ __launch_bounds__(256)
void attn_sm(__half* __restrict__ p) {
    const int wid = threadIdx.x >> 5, lane = threadIdx.x & 31;
    const int t = blockIdx.x * 8 + wid;
    const int h = blockIdx.y, b = blockIdx.z;
    __half* row = p + ((size_t)((b * HH + h) * TT + t)) * TT;
    const int valid = t + 1;
    const int nj = (t >> 7) + 1;

    float4 v[8];
    float m = -INFINITY;
#pragma unroll
    for (int j = 0; j < 8; j++) {
        if (j < nj) {
            int c0 = j * 128 + lane * 4;
            uint2 u = *(const uint2*)(row + c0);
            float2 f0 = __half22float2(*(__half2*)&u.x);
            float2 f1 = __half22float2(*(__half2*)&u.y);
            float4 val;
            val.x = (c0 + 0 < valid) ? f0.x : -INFINITY;
            val.y = (c0 + 1 < valid) ? f0.y : -INFINITY;
            val.z = (c0 + 2 < valid) ? f1.x : -INFINITY;
            val.w = (c0 + 3 < valid) ? f1.y : -INFINITY;
            v[j] = val;
            m = fmaxf(m, fmaxf(fmaxf(val.x, val.y), fmaxf(val.z, val.w)));
        }
    }
#pragma unroll
    for (int o = 16; o; o >>= 1) m = fmaxf(m, __shfl_xor_sync(~0u, m, o));

    float sum = 0.f;
#pragma unroll
    for (int j = 0; j < 8; j++) {
        if (j < nj) {
            float2 e0 = exp2_pair((v[j].x - m) * L2E, (v[j].y - m) * L2E);
            float2 e1 = exp2_pair((v[j].z - m) * L2E, (v[j].w - m) * L2E);
            v[j] = make_float4(e0.x, e0.y, e1.x, e1.y);
            sum += e0.x + e0.y + e1.x + e1.y;
        }
    }
#pragma unroll
    for (int o = 16; o; o >>= 1) sum += __shfl_xor_sync(~0u, sum, o);
    float inv = 1.f / sum;
#pragma unroll
    for (int j = 0; j < 8; j++) {
        if (j < nj) {
            int c0 = j * 128 + lane * 4;
            __half2 h0 = __floats2half2_rn(v[j].x * inv, v[j].y * inv);
            __half2 h1 = __floats2half2_rn(v[j].z * inv, v[j].w * inv);
            uint2 u;
            u.x = *(uint32_t*)&h0; u.y = *(uint32_t*)&h1;
            *(uint2*)(row + c0) = u;
        }
    }
}

// ---------------- loss: single-pass online softmax ------------------------------
__global__ void loss_row_k(const float* __restrict__ logits, const int* __restrict__ tgt,
                           float* __restrict__ rl) {
    int row = blockIdx.x, tid = threadIdx.x;  // 256 threads, VV/4 = 8000 vec4
    const float4* lr4 = (const float4*)(logits + (size_t)row * VV);
    __shared__ float rm[256], rs[256];

    float m = -INFINITY, s = 0.f;
    for (int i = tid; i < VV / 4; i += 256) {
        float4 v = lr4[i];
        float m4 = fmaxf(fmaxf(v.x, v.y), fmaxf(v.z, v.w));
        if (m4 > m) {
            s *= exp2f((m - m4) * L2E);   // fp32 rescale (rare path after warmup)
            m = m4;
        }
        float2 e0 = exp2_pair((v.x - m) * L2E, (v.y - m) * L2E);
        float2 e1 = exp2_pair((v.z - m) * L2E, (v.w - m) * L2E);
        s += e0.x + e0.y + e1.x + e1.y;
    }
    rm[tid] = m; rs[tid] = s;
    __syncthreads();
    for (int k = 128; k > 0; k >>= 1) {
        if (tid < k) {
            float ma = rm[tid], mb = rm[tid + k];
            float mx = fmaxf(ma, mb);
            rs[tid] = rs[tid] * exp2f((ma - mx) * L2E)
                    + rs[tid + k] * exp2f((mb - mx) * L2E);
            rm[tid] = mx;
        }
        __syncthreads();
    }
    if (tid == 0) {
        float lse = rm[0] + logf(rs[0]);
        rl[row] = lse - logits[(size_t)row * VV + tgt[row]];
    }
}

__global__ void loss_final_k(const float* __restrict__ rl, float* __restrict__ out) {
    __shared__ float red[256];
    int tid = threadIdx.x;
    float s = 0.f;
    for (int i = tid; i < ROWS; i += 256) s += rl[i];
    red[tid] = s; __syncthreads();
    for (int k = 128; k > 0; k >>= 1) { if (tid < k) red[tid] += red[tid + k]; __syncthreads(); }
    if (tid == 0) out[0] = red[0] * (1.0f / ROWS);
}

__global__ void fill0_k(float* p, size_t n) {
    size_t i = (size_t)blockIdx.x * blockDim.x + threadIdx.x;
    if (i < n) p[i] = 0.f;
}

// ---------------- host-side launcher -------------------------------------------
static inline void gemm(const __half* A, const __half* B, void* C,
                        int M, int N, int K, int lda, int ldb, int ldc,
                        int Nh, size_t hs, const float* bias, int flags,
                        int batch = 1, int batchH = 1,
                        size_t aO = 0, size_t aI = 0,
                        size_t bO = 0, size_t bI = 0,
                        size_t cO = 0, size_t cI = 0) {
    dim3 grid(N / 128, M / 128, batch);
    gemm_hc<<<grid, 256, GSMEM>>>(A, B, C, K, lda, ldb, ldc, Nh, hs, bias, flags,
                                  batchH, aO, aI, bO, bI, cO, cI);
}

extern "C" void kernel_launch(void* const* d_in, const int* in_sizes, int n_in,
                              void* d_out, int out_size) {
    const int*   ids   = (const int*)d_in[0];
    const int*   tgt   = (const int*)d_in[1];
    const float* tok   = (const float*)d_in[2];
    const float* pos   = (const float*)d_in[3];
    const float* Wq_i  = (const float*)d_in[4];
    const float* Wk_i  = (const float*)d_in[5];
    const float* Wv_i  = (const float*)d_in[6];
    const float* Wp_i  = (const float*)d_in[7];
    const float* bproj = (const float*)d_in[8];
    const float* ln1g  = (const float*)d_in[9];
    const float* ln1b  = (const float*)d_in[10];
    const float* ln2g  = (const float*)d_in[11];
    const float* ln2b  = (const float*)d_in[12];
    const float* W1_i  = (const float*)d_in[13];
    const float* b1    = (const float*)d_in[14];
    const float* W2_i  = (const float*)d_in[15];
    const float* b2    = (const float*)d_in[16];
    const float* lnfg  = (const float*)d_in[17];
    const float* lnfb  = (const float*)d_in[18];
    const float* Wh_i  = (const float*)d_in[19];
    const float* bhead = (const float*)d_in[20];

    float *x, *sk, *rl;
    __half *h, *qk, *v, *o, *p, *f, *wc;
    cudaGetSymbolAddress((void**)&x, g_x);
    cudaGetSymbolAddress((void**)&h, g_h);
    cudaGetSymbolAddress((void**)&qk, g_qk);
    cudaGetSymbolAddress((void**)&v, g_v);
    cudaGetSymbolAddress((void**)&o, g_o);
    cudaGetSymbolAddress((void**)&p, g_p);
    cudaGetSymbolAddress((void**)&f, g_f);
    cudaGetSymbolAddress((void**)&sk, g_sk);
    cudaGetSymbolAddress((void**)&rl, g_rl);
    cudaGetSymbolAddress((void**)&wc, g_wc);

    static bool attrSet = false;
    if (!attrSet) {
        cudaFuncSetAttribute(gemm_hc, cudaFuncAttributeMaxDynamicSharedMemorySize, GSMEM);
        cudaFuncSetAttribute(score_tc, cudaFuncAttributeMaxDynamicSharedMemorySize, SSMEM);
        attrSet = true;
    }

    __half* Wq = wc + O_WQ;  __half* Wk = wc + O_WK;  __half* Wv = wc + O_WV;
    __half* Wp = wc + O_WP;  __half* W1 = wc + O_W1;  __half* W2 = wc + O_W2;
    __half* Wh = wc + O_WH;
    __half* q = qk;
    __half* k = qk + (size_t)ROWS * DD;

    float* out = (float*)d_out;
    const size_t NL = (size_t)ROWS * VV;

    embed_k<<<ROWS, 256>>>(ids, tok, pos, x);
    cvt_k<<<1024, 256>>>((const float4*)Wq_i, (uint2*)Wq, (size_t)WQ_SZ / 4);
    cvt_k<<<1024, 256>>>((const float4*)Wk_i, (uint2*)Wk, (size_t)WQ_SZ / 4);
    ln_k<<<ROWS / 8, 256>>>(x, h, ln1g, ln1b);
    cvt_k<<<2048, 256>>>((const float4*)Wv_i, (uint2*)Wv, (size_t)WV_SZ / 4);
    // merged q/k projection for layer 0
    gemm(h, Wq, q, ROWS, DD, DD, DD, KH, DD, KH, (size_t)DD * KH, nullptr, 32,
         2, 1, 0, 0, (size_t)WQ_SZ, 0, (size_t)ROWS * DD, 0);
    cvt_k<<<2048, 256>>>((const float4*)Wp_i, (uint2*)Wp, (size_t)WP_SZ / 4);
    cvt_k<<<1024, 256>>>((const float4*)W1_i, (uint2*)W1, (size_t)W1_SZ / 4);
    cvt_k<<<1024, 256>>>((const float4*)W2_i, (uint2*)W2, (size_t)W1_SZ / 4);
    cvt_k<<<2048, 256>>>((const float4*)Wh_i, (uint2*)Wh, (size_t)WH_SZ / 4);

    for (int l = 0; l < LL; l++) {
        if (l > 0) {
            gemm(h, Wq + (size_t)l * HH * DD * KH, q, ROWS, DD, DD, DD, KH, DD,
                 KH, (size_t)DD * KH, nullptr, 32,
                 2, 1, 0, 0, (size_t)WQ_SZ, 0, (size_t)ROWS * DD, 0);
        }
        gemm(h, Wv + (size_t)l * HH * DD * DD, v, ROWS, HD, DD, DD, DD, HD,
             DD, (size_t)DD * DD, nullptr, 32);
        {
            dim3 grid(TT / 128, TT / 128, BSZ * HH);
            score_tc<<<grid, 256, SSMEM>>>(q, k, p);
            dim3 grid2(TT / 8, HH, BSZ);
            attn_sm<<<grid2, 256>>>(p);
        }
        gemm(p, v, o, TT, DD, TT, TT, HD, HD, DD, 0, nullptr, 8 | 32,
             BSZ * HH, HH,
             (size_t)HH * TT * TT, (size_t)TT * TT,
             (size_t)TT * HD, (size_t)DD,
             (size_t)TT * HD, (size_t)DD);
        // proj: split-K x2 (fp32 partials), fused combine + ln2 -> h
        gemm(o, Wp + (size_t)l * HD * DD, sk, ROWS, DD, HD / 2, HD, DD, DD,
             DD, 0, nullptr, 0,
             2, 1, (size_t)(HD / 2), 0, (size_t)(HD / 2) * DD, 0, (size_t)ROWS * DD, 0);
        addskln_k<<<ROWS / 8, 256>>>((const float4*)sk,
                                     (const float4*)(sk + (size_t)ROWS * DD),
                                     bproj + l * DD, (float4*)x,
                                     ln2g + l * DD, ln2b + l * DD, h);
        gemm(h, W1 + (size_t)l * DD * FF, f, ROWS, FF, DD, DD, FF, FF,
             FF, 0, b1 + l * FF, 1 | 2 | 32);
        gemm(f, W2 + (size_t)l * FF * DD, sk, ROWS, DD, FF / 2, FF, DD, DD,
             DD, 0, nullptr, 0,
             2, 1, (size_t)(FF / 2), 0, (size_t)(FF / 2) * DD, 0, (size_t)ROWS * DD, 0);
        // fused combine + (ln1 of next layer, or final ln) -> h
        const float* ng = (l + 1 < LL) ? (ln1g + (l + 1) * DD) : lnfg;
        const float* nb = (l + 1 < LL) ? (ln1b + (l + 1) * DD) : lnfb;
        addskln_k<<<ROWS / 8, 256>>>((const float4*)sk,
                                     (const float4*)(sk + (size_t)ROWS * DD),
                                     b2 + l * DD, (float4*)x, ng, nb, h);
    }

    gemm(h, Wh, out, ROWS, VV, DD, DD, VV, VV, VV, 0, bhead, 1);
    loss_row_k<<<ROWS, 256>>>(out, tgt, rl);
    if ((size_t)out_size >= NL + 1) {
        loss_final_k<<<1, 256>>>(rl, out + NL);
        size_t tail = (size_t)out_size - (NL + 1);
        if (tail > 0)
            fill0_k<<<(int)((tail + 255) / 256), 256>>>(out + NL + 1, tail);
    }
}